// round 5
// baseline (speedup 1.0000x reference)
#include <cuda_runtime.h>
#include <math.h>

#define NTOT   160000   // B*N flattened nodes
#define NNODE  5000
#define NEDGE  80000
#define TSTEPS 12
#define BATCH  32
#define HD     128
#define HORZ   12
#define INF    2

// ---------------- static device scratch (no allocation allowed) ----------------
__device__ float g_h   [NTOT * HD];        // hidden state
__device__ float g_hc  [NTOT * HD];        // cheb_conv(h)
__device__ float g_zr  [NTOT * 2 * HD];    // [z | r] gates
__device__ float g_f   [NTOT * 6];         // rank-6 ic features per node
__device__ float g_P1  [NNODE * HD];       // prop(h)
__device__ float g_P2  [NNODE * HD];       // prop(prop(h))
__device__ float g_X1  [NNODE * INF];      // prop(x_t)
__device__ float g_X2  [NNODE * INF];      // prop(prop(x_t))
__device__ float g_norm[NEDGE];
__device__ int   g_degsrc[NNODE];
__device__ int   g_cnt [NNODE];
__device__ int   g_off [NNODE + 1];
__device__ int   g_cur [NNODE];
__device__ int   g_csrsrc[NEDGE];
__device__ float g_csrw  [NEDGE];
__device__ float g_A2eff [HD * HD];        // W2[0]-W2[2]
__device__ float g_Wzrb  [HD * 2 * HD];    // bottom rows of [Wz|Wr] : [128,256]
__device__ float g_M6zr  [6 * 2 * HD];     // rank-6 ic -> zr gates
__device__ float g_biaszr[2 * HD];
__device__ float g_M6c   [6 * HD];         // rank-6 ic -> candidate
__device__ float g_biasc [HD];
__device__ int   g_bad64;                  // edge dtype probe
__device__ int   g_is64;

// ---------------- packed fp32x2 FMA ----------------
__device__ __forceinline__ unsigned long long ffma2(unsigned long long a,
                                                    unsigned long long b,
                                                    unsigned long long c) {
    unsigned long long d;
    asm("fma.rn.f32x2 %0, %1, %2, %3;" : "=l"(d) : "l"(a), "l"(b), "l"(c));
    return d;
}
__device__ __forceinline__ float2 unpack2(unsigned long long v) {
    float2 r;
    asm("mov.b64 {%0, %1}, %2;" : "=f"(r.x), "=f"(r.y) : "l"(v));
    return r;
}

// ---------------- edge_index dtype handling ----------------
__global__ void detect_dtype_kernel(const void* __restrict__ ei) {
    int e = blockIdx.x * blockDim.x + threadIdx.x;
    if (e >= 2 * NEDGE) return;
    long long v = ((const long long*)ei)[e];
    if (v < 0 || v >= NNODE) atomicOr(&g_bad64, 1);
}
__global__ void set_is64_kernel() { g_is64 = g_bad64 ? 0 : 1; }

__device__ __forceinline__ int edge_at(const void* __restrict__ ei, int idx) {
    int s;
    if (g_is64) s = (int)((const long long*)ei)[idx];
    else        s = ((const int*)ei)[idx];
    if (s < 0) s = 0;
    if (s >= NNODE) s = NNODE - 1;
    return s;
}

// ---------------- tiny setup kernels ----------------
__global__ void zero_h_kernel() {
    int i = blockIdx.x * blockDim.x + threadIdx.x;
    if (i < NTOT * HD) g_h[i] = 0.f;
}

__global__ void zero_counts_kernel() {
    int i = blockIdx.x * blockDim.x + threadIdx.x;
    if (i < NNODE) g_degsrc[i] = 0;
    else if (i < 2 * NNODE) g_cnt[i - NNODE] = 0;
    if (i == 0) g_bad64 = 0;
}

__global__ void count_edges_kernel(const void* __restrict__ ei) {
    int e = blockIdx.x * blockDim.x + threadIdx.x;
    if (e >= NEDGE) return;
    int s = edge_at(ei, e);
    int d = edge_at(ei, NEDGE + e);
    atomicAdd(&g_degsrc[s], 1);
    atomicAdd(&g_cnt[d], 1);
}

__global__ void norm_kernel(const void* __restrict__ ei) {
    int e = blockIdx.x * blockDim.x + threadIdx.x;
    if (e >= NEDGE) return;
    int s = edge_at(ei, e);
    int d = edge_at(ei, NEDGE + e);
    int ds = g_degsrc[s], dd = g_degsrc[d];
    float is = (ds > 0) ? rsqrtf((float)ds) : 0.f;
    float id = (dd > 0) ? rsqrtf((float)dd) : 0.f;
    g_norm[e] = -is * id;
}

__global__ void scan_kernel() {   // exclusive scan of g_cnt -> g_off/g_cur
    __shared__ int sh[1024];
    int t = threadIdx.x;
    int start = t * 5;
    int end = start + 5; if (end > NNODE) end = NNODE;
    int s = 0;
    for (int i = start; i < end && i < NNODE; i++) s += g_cnt[i];
    sh[t] = s;
    __syncthreads();
    for (int off = 1; off < 1024; off <<= 1) {
        int v = (t >= off) ? sh[t - off] : 0;
        __syncthreads();
        sh[t] += v;
        __syncthreads();
    }
    int run = (t == 0) ? 0 : sh[t - 1];
    for (int i = start; i < end && i < NNODE; i++) {
        g_off[i] = run; g_cur[i] = run; run += g_cnt[i];
    }
    if (t == 1023) g_off[NNODE] = sh[1023];
}

__global__ void fill_kernel(const void* __restrict__ ei) {
    int e = blockIdx.x * blockDim.x + threadIdx.x;
    if (e >= NEDGE) return;
    int s = edge_at(ei, e);
    int d = edge_at(ei, NEDGE + e);
    int p = atomicAdd(&g_cur[d], 1);
    if (p >= NEDGE) p = NEDGE - 1;
    g_csrsrc[p] = s;
    g_csrw[p]   = g_norm[e];
}

__global__ void build_A2eff_kernel(const float* __restrict__ W2) {
    int i = blockIdx.x * blockDim.x + threadIdx.x;
    if (i < HD * HD) g_A2eff[i] = W2[i] - W2[2 * HD * HD + i];
}

__global__ void build_Wzrb_kernel(const float* __restrict__ Wz, const float* __restrict__ Wr) {
    int i = blockIdx.x * blockDim.x + threadIdx.x;
    if (i >= HD * 2 * HD) return;
    int k = i >> 8;
    int j = i & 255;
    g_Wzrb[i] = (j < HD) ? Wz[(HD + k) * HD + j] : Wr[(HD + k) * HD + (j - HD)];
}

__device__ __forceinline__ float ic_row_elem(const float* W1, const float* b1, int r, int k) {
    switch (r) {
        case 0: return W1[k]        - W1[512 + k];
        case 1: return W1[128 + k]  - W1[640 + k];
        case 2: return W1[256 + k];
        case 3: return W1[384 + k];
        case 4: return 2.f * W1[512 + k];
        case 5: return 2.f * W1[640 + k];
        default: return b1[k];
    }
}

__global__ void build_zr_fold_kernel(const float* __restrict__ W1, const float* __restrict__ b1,
                                     const float* __restrict__ Wz, const float* __restrict__ bz,
                                     const float* __restrict__ Wr, const float* __restrict__ br) {
    int idx = blockIdx.x * blockDim.x + threadIdx.x;
    if (idx >= 7 * 256) return;
    int r = idx / 256, j = idx % 256;
    const float* Wtop = (j < HD) ? Wz : Wr;
    int jj = j & (HD - 1);
    float s = 0.f;
    for (int k = 0; k < HD; k++) s += ic_row_elem(W1, b1, r, k) * Wtop[k * HD + jj];
    if (r < 6) g_M6zr[r * 256 + j] = s;
    else       g_biaszr[j] = s + ((j < HD) ? bz[jj] : br[jj]);
}

__global__ void build_c_fold_kernel(const float* __restrict__ W1, const float* __restrict__ b1,
                                    const float* __restrict__ Wc, const float* __restrict__ bc) {
    int idx = blockIdx.x * blockDim.x + threadIdx.x;
    if (idx >= 7 * HD) return;
    int r = idx / HD, j = idx % HD;
    float s = 0.f;
    for (int k = 0; k < HD; k++) s += ic_row_elem(W1, b1, r, k) * Wc[k * HD + j];
    if (r < 6) g_M6c[r * HD + j] = s;
    else       g_biasc[j] = s + bc[j];
}

// ---------------- graph propagation (CSR gather) ----------------
__global__ void prop128_kernel(int sel) {
    const float* tin  = sel ? g_P1 : g_h;
    float*       tout = sel ? g_P2 : g_P1;
    int d = blockIdx.x, j = threadIdx.x;
    int p0 = g_off[d], p1 = g_off[d + 1];
    float acc = 0.f;
    for (int p = p0; p < p1; p++)
        acc = fmaf(g_csrw[p], tin[g_csrsrc[p] * HD + j], acc);
    tout[d * HD + j] = acc;
}

__global__ void prop2_kernel(const float* __restrict__ xin, int sel) {
    int idx = blockIdx.x * blockDim.x + threadIdx.x;
    if (idx >= NNODE * INF) return;
    int d = idx >> 1, c = idx & 1;
    const float* tin  = sel ? g_X1 : xin;
    float*       tout = sel ? g_X2 : g_X1;
    int p0 = g_off[d], p1 = g_off[d + 1];
    float acc = 0.f;
    for (int p = p0; p < p1; p++)
        acc = fmaf(g_csrw[p], tin[g_csrsrc[p] * INF + c], acc);
    tout[idx] = acc;
}

__global__ void build_f_kernel(const float* __restrict__ x, int t) {
    int i = blockIdx.x * blockDim.x + threadIdx.x;
    if (i >= NTOT) return;
    int b = i / NNODE, n = i - b * NNODE;
    const float* xr = x + ((size_t)(b * TSTEPS + t) * NNODE + n) * INF;
    float* f = g_f + (size_t)i * 6;
    f[0] = xr[0]; f[1] = xr[1];
    if (i < NNODE) {
        f[2] = g_X1[i * 2];     f[3] = g_X1[i * 2 + 1];
        f[4] = g_X2[i * 2];     f[5] = g_X2[i * 2 + 1];
    } else {
        f[2] = 0.f; f[3] = 0.f; f[4] = 0.f; f[5] = 0.f;
    }
}

// ---------------- fused SGEMM with packed fp32x2 FMAs ----------------
// MODE 0: g_hc = A@B + bias          (hc main)
// MODE 3: g_hc += A@B                (5000-row cheb correction; A=[P1|2*P2], K=256)
// MODE 1: g_zr = sigmoid(A@B + f@M6zr + biaszr)          (A=hc)
// MODE 2: g_h  = z*h + (1-z)*tanh(A@B + f@M6c + biasc)   (A=r.*hc, USE_R)
#define BM 128
#define BN 128
#define BK 16

template <int MODE, bool USE_A2, bool USE_R>
__global__ __launch_bounds__(256)
void gemm2_kernel(int aSel, const float* __restrict__ Bext, const float* __restrict__ biasExt,
                  int M, int Ncols, int Ktot, float a2scale) {
    const float* A1;
    const float* A2 = nullptr;
    if (aSel == 0)      A1 = g_h;
    else if (aSel == 1) A1 = g_hc;
    else              { A1 = g_P1; A2 = g_P2; }
    const float* B = Bext ? Bext : (MODE == 0 ? g_A2eff : g_Wzrb);

    __shared__ __align__(16) float As[BK][2 * BM];   // duplicated: As[k][2r]=As[k][2r+1]=A[r][k]
    __shared__ __align__(16) float Bs[BK][BN];

    int tid  = threadIdx.x;
    int row0 = blockIdx.y * BM;
    int col0 = blockIdx.x * BN;

    unsigned long long acc[8][4];
#pragma unroll
    for (int i = 0; i < 8; i++)
#pragma unroll
        for (int j = 0; j < 4; j++) acc[i][j] = 0ull;

    int arow = tid >> 1;            // 0..127
    int ak   = (tid & 1) << 3;      // 0 or 8
    int brow = tid >> 4;            // 0..15 : k-row of B tile
    int bcol = (tid & 15) << 3;     // 0..120 step 8
    int ty   = tid >> 4;            // 0..15 : 8-row group
    int tx   = tid & 15;            // 0..15 : 8-col group

    for (int kt = 0; kt < Ktot; kt += BK) {
        // ---- A tile load (with optional r-gating / [P1|2*P2] concat), duplicated store
        int gr = row0 + arow;
#pragma unroll
        for (int q = 0; q < 2; q++) {
            int gk = kt + ak + q * 4;
            float4 av = make_float4(0.f, 0.f, 0.f, 0.f);
            if (gr < M) {
                if (!USE_A2 || gk < 128) {
                    av = *reinterpret_cast<const float4*>(A1 + (size_t)gr * 128 + gk);
                    if (USE_R) {
                        float4 rv = *reinterpret_cast<const float4*>(g_zr + (size_t)gr * 256 + 128 + gk);
                        av.x *= rv.x; av.y *= rv.y; av.z *= rv.z; av.w *= rv.w;
                    }
                } else {
                    av = *reinterpret_cast<const float4*>(A2 + (size_t)gr * 128 + (gk - 128));
                    av.x *= a2scale; av.y *= a2scale; av.z *= a2scale; av.w *= a2scale;
                }
            }
            int kk = ak + q * 4;
            *reinterpret_cast<float2*>(&As[kk + 0][2 * arow]) = make_float2(av.x, av.x);
            *reinterpret_cast<float2*>(&As[kk + 1][2 * arow]) = make_float2(av.y, av.y);
            *reinterpret_cast<float2*>(&As[kk + 2][2 * arow]) = make_float2(av.z, av.z);
            *reinterpret_cast<float2*>(&As[kk + 3][2 * arow]) = make_float2(av.w, av.w);
        }
        // ---- B tile load
        {
            const float* bp = B + (size_t)(kt + brow) * Ncols + col0 + bcol;
            float4 b0 = *reinterpret_cast<const float4*>(bp);
            float4 b1 = *reinterpret_cast<const float4*>(bp + 4);
            *reinterpret_cast<float4*>(&Bs[brow][bcol])     = b0;
            *reinterpret_cast<float4*>(&Bs[brow][bcol + 4]) = b1;
        }
        __syncthreads();

#pragma unroll
        for (int k = 0; k < BK; k++) {
            const ulonglong2* ap = reinterpret_cast<const ulonglong2*>(&As[k][ty << 4]);
            ulonglong2 a01 = ap[0], a23 = ap[1], a45 = ap[2], a67 = ap[3];
            const ulonglong2* bp = reinterpret_cast<const ulonglong2*>(&Bs[k][tx << 3]);
            ulonglong2 b03 = bp[0], b47 = bp[1];
            unsigned long long a_[8] = {a01.x, a01.y, a23.x, a23.y, a45.x, a45.y, a67.x, a67.y};
            unsigned long long b_[4] = {b03.x, b03.y, b47.x, b47.y};
#pragma unroll
            for (int i = 0; i < 8; i++) {
#pragma unroll
                for (int j = 0; j < 4; j++)
                    acc[i][j] = ffma2(a_[i], b_[j], acc[i][j]);
            }
        }
        __syncthreads();
    }

    // ---- fused epilogues
#pragma unroll
    for (int i = 0; i < 8; i++) {
        int gr = row0 + (ty << 3) + i;
        if (gr >= M) break;
        float fv0 = 0, fv1 = 0, fv2 = 0, fv3 = 0, fv4 = 0, fv5 = 0;
        if (MODE == 1 || MODE == 2) {
            const float* f = g_f + (size_t)gr * 6;
            fv0 = f[0]; fv1 = f[1]; fv2 = f[2]; fv3 = f[3]; fv4 = f[4]; fv5 = f[5];
        }
#pragma unroll
        for (int j = 0; j < 4; j++) {
            float2 vp = unpack2(acc[i][j]);
#pragma unroll
            for (int half = 0; half < 2; half++) {
                int gc = col0 + (tx << 3) + 2 * j + half;
                float v = half ? vp.y : vp.x;
                if (MODE == 0) {
                    g_hc[(size_t)gr * 128 + gc] = v + biasExt[gc];
                } else if (MODE == 3) {
                    g_hc[(size_t)gr * 128 + gc] += v;
                } else if (MODE == 1) {
                    v += g_biaszr[gc]
                       + fv0 * g_M6zr[gc]        + fv1 * g_M6zr[256 + gc]
                       + fv2 * g_M6zr[512 + gc]  + fv3 * g_M6zr[768 + gc]
                       + fv4 * g_M6zr[1024 + gc] + fv5 * g_M6zr[1280 + gc];
                    g_zr[(size_t)gr * 256 + gc] = 1.f / (1.f + expf(-v));
                } else {  // MODE 2 : fused GRU update, in-place h
                    v += g_biasc[gc]
                       + fv0 * g_M6c[gc]       + fv1 * g_M6c[128 + gc]
                       + fv2 * g_M6c[256 + gc] + fv3 * g_M6c[384 + gc]
                       + fv4 * g_M6c[512 + gc] + fv5 * g_M6c[640 + gc];
                    float z  = g_zr[(size_t)gr * 256 + gc];
                    float hp = g_h[(size_t)gr * 128 + gc];
                    g_h[(size_t)gr * 128 + gc] = z * hp + (1.f - z) * tanhf(v);
                }
            }
        }
    }
}

// ---------------- output head ----------------
__global__ void out_kernel(const float* __restrict__ Wo, const float* __restrict__ bo,
                           float* __restrict__ out) {
    int idx = blockIdx.x * blockDim.x + threadIdx.x;
    if (idx >= NTOT * HORZ) return;
    int i = idx / HORZ, hor = idx - i * HORZ;
    const float* hr = g_h + (size_t)i * HD;
    float s = bo[hor];
#pragma unroll 8
    for (int k = 0; k < HD; k++) s = fmaf(hr[k], Wo[k * HORZ + hor], s);
    int b = i / NNODE, n = i - b * NNODE;
    out[(size_t)(b * HORZ + hor) * NNODE + n] = s;
}

// ---------------- launch ----------------
extern "C" void kernel_launch(void* const* d_in, const int* in_sizes, int n_in,
                              void* d_out, int out_size) {
    const float* x  = (const float*)d_in[0];
    const void*  ei = d_in[1];
    const float* W1 = (const float*)d_in[2];
    const float* b1 = (const float*)d_in[3];
    const float* W2 = (const float*)d_in[4];
    const float* b2 = (const float*)d_in[5];
    const float* Wz = (const float*)d_in[6];
    const float* bz = (const float*)d_in[7];
    const float* Wr = (const float*)d_in[8];
    const float* br = (const float*)d_in[9];
    const float* Wc = (const float*)d_in[10];
    const float* bc = (const float*)d_in[11];
    const float* Wo = (const float*)d_in[12];
    const float* bo = (const float*)d_in[13];
    float* out = (float*)d_out;
    (void)in_sizes; (void)n_in; (void)out_size;

    // setup
    zero_h_kernel<<<(NTOT * HD + 1023) / 1024, 1024>>>();
    zero_counts_kernel<<<(2 * NNODE + 255) / 256, 256>>>();
    detect_dtype_kernel<<<(2 * NEDGE + 255) / 256, 256>>>(ei);
    set_is64_kernel<<<1, 1>>>();
    count_edges_kernel<<<(NEDGE + 255) / 256, 256>>>(ei);
    norm_kernel<<<(NEDGE + 255) / 256, 256>>>(ei);
    scan_kernel<<<1, 1024>>>();
    fill_kernel<<<(NEDGE + 255) / 256, 256>>>(ei);
    build_A2eff_kernel<<<(HD * HD + 255) / 256, 256>>>(W2);
    build_Wzrb_kernel<<<(HD * 2 * HD + 255) / 256, 256>>>(Wz, Wr);
    build_zr_fold_kernel<<<(7 * 256 + 255) / 256, 256>>>(W1, b1, Wz, bz, Wr, br);
    build_c_fold_kernel<<<(7 * HD + 255) / 256, 256>>>(W1, b1, Wc, bc);

    for (int t = 0; t < TSTEPS; t++) {
        const float* xt0 = x + (size_t)t * NNODE * INF;   // batch 0, timestep t
        prop2_kernel<<<(NNODE * INF + 127) / 128, 128>>>(xt0, 0);
        prop2_kernel<<<(NNODE * INF + 127) / 128, 128>>>(xt0, 1);
        prop128_kernel<<<NNODE, HD>>>(0);
        prop128_kernel<<<NNODE, HD>>>(1);
        build_f_kernel<<<(NTOT + 255) / 256, 256>>>(x, t);

        // hc = h @ (W2[0]-W2[2]) + b2
        gemm2_kernel<0, false, false><<<dim3(1, NTOT / BM), 256>>>(
            0, nullptr, b2, NTOT, 128, 128, 1.f);
        // hc[0:5000] += P1@W2[1] + 2*P2@W2[2]
        gemm2_kernel<3, true, false><<<dim3(1, (NNODE + BM - 1) / BM), 256>>>(
            2, W2 + HD * HD, nullptr, NNODE, 128, 256, 2.f);
        // zr = sigmoid(hc @ Wzr_bot + f@M6zr + biaszr)
        gemm2_kernel<1, false, false><<<dim3(2, NTOT / BM), 256>>>(
            1, nullptr, nullptr, NTOT, 256, 128, 1.f);
        // h = z*h + (1-z)*tanh((r.*hc) @ Wc_bot + f@M6c + biasc)
        gemm2_kernel<2, false, true><<<dim3(1, NTOT / BM), 256>>>(
            1, Wc + HD * HD, nullptr, NTOT, 128, 128, 1.f);
    }

    out_kernel<<<(NTOT * HORZ + 255) / 256, 256>>>(Wo, bo, out);
}

// round 6
// speedup vs baseline: 1.9571x; 1.9571x over previous
#include <cuda_runtime.h>
#include <cuda_bf16.h>
#include <math.h>

#define NTOT   160000   // B*N flattened nodes
#define NNODE  5000
#define NEDGE  80000
#define TSTEPS 12
#define BATCH  32
#define HD     128
#define HORZ   12
#define INF    2

// ---------------- static device scratch (no allocation allowed) ----------------
__device__ float g_h   [NTOT * HD];        // hidden state
__device__ float g_hc  [NTOT * HD];        // cheb_conv(h)
__device__ float g_zr  [NTOT * 2 * HD];    // [z | r] gates
__device__ float g_f   [NTOT * 6];         // rank-6 ic features per node
__device__ float g_P1  [NNODE * HD];       // prop(h)
__device__ float g_P2  [NNODE * HD];       // prop(prop(h))
__device__ float g_X1  [NNODE * INF];      // prop(x_t)
__device__ float g_X2  [NNODE * INF];      // prop(prop(x_t))
__device__ float g_norm[NEDGE];
__device__ int   g_degsrc[NNODE];
__device__ int   g_cnt [NNODE];
__device__ int   g_off [NNODE + 1];
__device__ int   g_cur [NNODE];
__device__ int   g_csrsrc[NEDGE];
__device__ float g_csrw  [NEDGE];
__device__ float g_M6zr  [6 * 2 * HD];     // rank-6 ic -> zr gates (fp32 epilogue)
__device__ float g_biaszr[2 * HD];
__device__ float g_M6c   [6 * HD];         // rank-6 ic -> candidate
__device__ float g_biasc [HD];
__device__ int   g_bad64;                  // edge dtype probe
__device__ int   g_is64;

// split-bf16 transposed weights [N][K], built once per launch
__device__ __align__(16) __nv_bfloat16 g_A2t_h [128 * 128];  // W2[0]-W2[2], [n][k]
__device__ __align__(16) __nv_bfloat16 g_A2t_l [128 * 128];
__device__ __align__(16) __nv_bfloat16 g_W2bt_h[128 * 256];  // [W2[1]; 2*W2[2]] stacked-K, [n][k]
__device__ __align__(16) __nv_bfloat16 g_W2bt_l[128 * 256];
__device__ __align__(16) __nv_bfloat16 g_Wzrt_h[256 * 128];  // bottom [Wz|Wr], [n][k]
__device__ __align__(16) __nv_bfloat16 g_Wzrt_l[256 * 128];
__device__ __align__(16) __nv_bfloat16 g_Wct_h [128 * 128];  // bottom Wc, [n][k]
__device__ __align__(16) __nv_bfloat16 g_Wct_l [128 * 128];

// ---------------- edge_index dtype handling ----------------
__global__ void detect_dtype_kernel(const void* __restrict__ ei) {
    int e = blockIdx.x * blockDim.x + threadIdx.x;
    if (e >= 2 * NEDGE) return;
    long long v = ((const long long*)ei)[e];
    if (v < 0 || v >= NNODE) atomicOr(&g_bad64, 1);
}
__global__ void set_is64_kernel() { g_is64 = g_bad64 ? 0 : 1; }

__device__ __forceinline__ int edge_at(const void* __restrict__ ei, int idx) {
    int s;
    if (g_is64) s = (int)((const long long*)ei)[idx];
    else        s = ((const int*)ei)[idx];
    if (s < 0) s = 0;
    if (s >= NNODE) s = NNODE - 1;
    return s;
}

// ---------------- tiny setup kernels ----------------
__global__ void zero_h_kernel() {
    int i = blockIdx.x * blockDim.x + threadIdx.x;
    if (i < NTOT * HD) g_h[i] = 0.f;
}

__global__ void zero_counts_kernel() {
    int i = blockIdx.x * blockDim.x + threadIdx.x;
    if (i < NNODE) g_degsrc[i] = 0;
    else if (i < 2 * NNODE) g_cnt[i - NNODE] = 0;
    if (i == 0) g_bad64 = 0;
}

__global__ void count_edges_kernel(const void* __restrict__ ei) {
    int e = blockIdx.x * blockDim.x + threadIdx.x;
    if (e >= NEDGE) return;
    int s = edge_at(ei, e);
    int d = edge_at(ei, NEDGE + e);
    atomicAdd(&g_degsrc[s], 1);
    atomicAdd(&g_cnt[d], 1);
}

__global__ void norm_kernel(const void* __restrict__ ei) {
    int e = blockIdx.x * blockDim.x + threadIdx.x;
    if (e >= NEDGE) return;
    int s = edge_at(ei, e);
    int d = edge_at(ei, NEDGE + e);
    int ds = g_degsrc[s], dd = g_degsrc[d];
    float is = (ds > 0) ? rsqrtf((float)ds) : 0.f;
    float id = (dd > 0) ? rsqrtf((float)dd) : 0.f;
    g_norm[e] = -is * id;
}

__global__ void scan_kernel() {   // exclusive scan of g_cnt -> g_off/g_cur
    __shared__ int sh[1024];
    int t = threadIdx.x;
    int start = t * 5;
    int end = start + 5; if (end > NNODE) end = NNODE;
    int s = 0;
    for (int i = start; i < end && i < NNODE; i++) s += g_cnt[i];
    sh[t] = s;
    __syncthreads();
    for (int off = 1; off < 1024; off <<= 1) {
        int v = (t >= off) ? sh[t - off] : 0;
        __syncthreads();
        sh[t] += v;
        __syncthreads();
    }
    int run = (t == 0) ? 0 : sh[t - 1];
    for (int i = start; i < end && i < NNODE; i++) {
        g_off[i] = run; g_cur[i] = run; run += g_cnt[i];
    }
    if (t == 1023) g_off[NNODE] = sh[1023];
}

__global__ void fill_kernel(const void* __restrict__ ei) {
    int e = blockIdx.x * blockDim.x + threadIdx.x;
    if (e >= NEDGE) return;
    int s = edge_at(ei, e);
    int d = edge_at(ei, NEDGE + e);
    int p = atomicAdd(&g_cur[d], 1);
    if (p >= NEDGE) p = NEDGE - 1;
    g_csrsrc[p] = s;
    g_csrw[p]   = g_norm[e];
}

// ---------------- split-bf16 weight build (transposed [n][k]) ----------------
__device__ __forceinline__ void bf_split(float v, __nv_bfloat16* hp, __nv_bfloat16* lp, int idx) {
    __nv_bfloat16 h = __float2bfloat16(v);
    float res = v - __bfloat162float(h);
    hp[idx] = h;
    lp[idx] = __float2bfloat16(res);
}

__global__ void build_bsplit_kernel(const float* __restrict__ W2, const float* __restrict__ Wz,
                                    const float* __restrict__ Wr, const float* __restrict__ Wc) {
    int i = blockIdx.x * blockDim.x + threadIdx.x;
    if (i < 16384) {                       // A2t : W2[0]-W2[2], [k][n] -> [n][k]
        int n = i >> 7, k = i & 127;
        float v = W2[k * 128 + n] - W2[2 * 16384 + k * 128 + n];
        bf_split(v, g_A2t_h, g_A2t_l, n * 128 + k);
    } else if (i < 49152) {                // W2bt : k<128 -> W2[1]; k>=128 -> 2*W2[2]
        int j = i - 16384; int n = j >> 8, k = j & 255;
        float v = (k < 128) ? W2[16384 + k * 128 + n]
                            : 2.f * W2[32768 + (k - 128) * 128 + n];
        bf_split(v, g_W2bt_h, g_W2bt_l, n * 256 + k);
    } else if (i < 81920) {                // Wzrt : bottom rows of [Wz|Wr]
        int j = i - 49152; int n = j >> 7, k = j & 127;
        float v = (n < 128) ? Wz[(128 + k) * 128 + n] : Wr[(128 + k) * 128 + (n - 128)];
        bf_split(v, g_Wzrt_h, g_Wzrt_l, n * 128 + k);
    } else if (i < 98304) {                // Wct : bottom rows of Wc
        int j = i - 81920; int n = j >> 7, k = j & 127;
        bf_split(Wc[(128 + k) * 128 + n], g_Wct_h, g_Wct_l, n * 128 + k);
    }
}

// ---------------- rank-6 ic folding (fp32 epilogue constants) ----------------
__device__ __forceinline__ float ic_row_elem(const float* W1, const float* b1, int r, int k) {
    switch (r) {
        case 0: return W1[k]        - W1[512 + k];
        case 1: return W1[128 + k]  - W1[640 + k];
        case 2: return W1[256 + k];
        case 3: return W1[384 + k];
        case 4: return 2.f * W1[512 + k];
        case 5: return 2.f * W1[640 + k];
        default: return b1[k];
    }
}

__global__ void build_zr_fold_kernel(const float* __restrict__ W1, const float* __restrict__ b1,
                                     const float* __restrict__ Wz, const float* __restrict__ bz,
                                     const float* __restrict__ Wr, const float* __restrict__ br) {
    int idx = blockIdx.x * blockDim.x + threadIdx.x;
    if (idx >= 7 * 256) return;
    int r = idx / 256, j = idx % 256;
    const float* Wtop = (j < HD) ? Wz : Wr;
    int jj = j & (HD - 1);
    float s = 0.f;
    for (int k = 0; k < HD; k++) s += ic_row_elem(W1, b1, r, k) * Wtop[k * HD + jj];
    if (r < 6) g_M6zr[r * 256 + j] = s;
    else       g_biaszr[j] = s + ((j < HD) ? bz[jj] : br[jj]);
}

__global__ void build_c_fold_kernel(const float* __restrict__ W1, const float* __restrict__ b1,
                                    const float* __restrict__ Wc, const float* __restrict__ bc) {
    int idx = blockIdx.x * blockDim.x + threadIdx.x;
    if (idx >= 7 * HD) return;
    int r = idx / HD, j = idx % HD;
    float s = 0.f;
    for (int k = 0; k < HD; k++) s += ic_row_elem(W1, b1, r, k) * Wc[k * HD + j];
    if (r < 6) g_M6c[r * HD + j] = s;
    else       g_biasc[j] = s + bc[j];
}

// ---------------- graph propagation (CSR gather) ----------------
__global__ void prop128_kernel(int sel) {
    const float* tin  = sel ? g_P1 : g_h;
    float*       tout = sel ? g_P2 : g_P1;
    int d = blockIdx.x, j = threadIdx.x;
    int p0 = g_off[d], p1 = g_off[d + 1];
    float acc = 0.f;
    for (int p = p0; p < p1; p++)
        acc = fmaf(g_csrw[p], tin[g_csrsrc[p] * HD + j], acc);
    tout[d * HD + j] = acc;
}

__global__ void prop2_kernel(const float* __restrict__ xin, int sel) {
    int idx = blockIdx.x * blockDim.x + threadIdx.x;
    if (idx >= NNODE * INF) return;
    int d = idx >> 1, c = idx & 1;
    const float* tin  = sel ? g_X1 : xin;
    float*       tout = sel ? g_X2 : g_X1;
    int p0 = g_off[d], p1 = g_off[d + 1];
    float acc = 0.f;
    for (int p = p0; p < p1; p++)
        acc = fmaf(g_csrw[p], tin[g_csrsrc[p] * INF + c], acc);
    tout[idx] = acc;
}

__global__ void build_f_kernel(const float* __restrict__ x, int t) {
    int i = blockIdx.x * blockDim.x + threadIdx.x;
    if (i >= NTOT) return;
    int b = i / NNODE, n = i - b * NNODE;
    const float* xr = x + ((size_t)(b * TSTEPS + t) * NNODE + n) * INF;
    float* f = g_f + (size_t)i * 6;
    f[0] = xr[0]; f[1] = xr[1];
    if (i < NNODE) {
        f[2] = g_X1[i * 2];     f[3] = g_X1[i * 2 + 1];
        f[4] = g_X2[i * 2];     f[5] = g_X2[i * 2 + 1];
    } else {
        f[2] = 0.f; f[3] = 0.f; f[4] = 0.f; f[5] = 0.f;
    }
}

// ---------------- split-bf16 tensor-core GEMM ----------------
// MODE 0: g_hc = h  @ A2t^T + b2
// MODE 3: g_hc += [P1|P2] @ W2bt^T         (K=256, 2x folded into B)
// MODE 1: g_zr = sigmoid(hc @ Wzrt^T + f@M6zr + biaszr)
// MODE 2: g_h  = z*h + (1-z)*tanh((r.*hc) @ Wct^T + f@M6c + biasc)
__device__ __forceinline__ void mma_bf16(float* c, const unsigned* a, const unsigned* b) {
    asm volatile(
        "mma.sync.aligned.m16n8k16.row.col.f32.bf16.bf16.f32 "
        "{%0,%1,%2,%3}, {%4,%5,%6,%7}, {%8,%9}, {%0,%1,%2,%3};\n"
        : "+f"(c[0]), "+f"(c[1]), "+f"(c[2]), "+f"(c[3])
        : "r"(a[0]), "r"(a[1]), "r"(a[2]), "r"(a[3]), "r"(b[0]), "r"(b[1]));
}

template <int MODE, int KTOT>
__global__ __launch_bounds__(256)
void mma_gemm(const float* __restrict__ biasExt, int M) {
    const __nv_bfloat16* Bh;
    const __nv_bfloat16* Bl;
    if (MODE == 0)      { Bh = g_A2t_h;  Bl = g_A2t_l;  }
    else if (MODE == 3) { Bh = g_W2bt_h; Bl = g_W2bt_l; }
    else if (MODE == 1) { Bh = g_Wzrt_h; Bl = g_Wzrt_l; }
    else                { Bh = g_Wct_h;  Bl = g_Wct_l;  }

    __shared__ __align__(16) __nv_bfloat16 As_h[128][16];
    __shared__ __align__(16) __nv_bfloat16 As_l[128][16];
    __shared__ __align__(16) __nv_bfloat16 Bs_h[64][16];
    __shared__ __align__(16) __nv_bfloat16 Bs_l[64][16];

    int tid  = threadIdx.x;
    int row0 = blockIdx.y * 128;
    int col0 = blockIdx.x * 64;
    int warp = tid >> 5, lane = tid & 31;
    int g = lane >> 2;            // 0..7
    int q = (lane & 3) << 1;      // 0,2,4,6

    float acc[8][4];
#pragma unroll
    for (int i = 0; i < 8; i++)
#pragma unroll
        for (int j = 0; j < 4; j++) acc[i][j] = 0.f;

    int srow  = tid >> 1;         // 0..127 A-staging row
    int skoff = (tid & 1) << 3;   // 0 or 8
    int bn    = (tid & 127) >> 1; // 0..63 B-staging row
    int bhalf = (tid & 1) << 3;
    bool doBl = (tid >= 128);

    for (int kt = 0; kt < KTOT; kt += 16) {
        // ---- stage A (fp32 -> split bf16 hi/lo)
        {
            int gr = row0 + srow;
            float a[8];
#pragma unroll
            for (int i = 0; i < 8; i++) a[i] = 0.f;
            if (gr < M) {
                int gk = kt + skoff;
                const float* src;
                if (MODE == 3) {
                    src = (gk < 128) ? (g_P1 + (size_t)gr * 128 + gk)
                                     : (g_P2 + (size_t)gr * 128 + (gk - 128));
                } else if (MODE == 0) {
                    src = g_h + (size_t)gr * 128 + gk;
                } else {
                    src = g_hc + (size_t)gr * 128 + gk;
                }
                float4 v0 = *(const float4*)(src);
                float4 v1 = *(const float4*)(src + 4);
                if (MODE == 2) {
                    const float* rp = g_zr + (size_t)gr * 256 + 128 + gk;
                    float4 r0 = *(const float4*)(rp);
                    float4 r1 = *(const float4*)(rp + 4);
                    v0.x *= r0.x; v0.y *= r0.y; v0.z *= r0.z; v0.w *= r0.w;
                    v1.x *= r1.x; v1.y *= r1.y; v1.z *= r1.z; v1.w *= r1.w;
                }
                a[0] = v0.x; a[1] = v0.y; a[2] = v0.z; a[3] = v0.w;
                a[4] = v1.x; a[5] = v1.y; a[6] = v1.z; a[7] = v1.w;
            }
            unsigned uh[4], ul[4];
#pragma unroll
            for (int i = 0; i < 4; i++) {
                __nv_bfloat16 h0 = __float2bfloat16(a[2 * i]);
                __nv_bfloat16 h1 = __float2bfloat16(a[2 * i + 1]);
                float l0 = a[2 * i]     - __bfloat162float(h0);
                float l1 = a[2 * i + 1] - __bfloat162float(h1);
                __nv_bfloat16 g0 = __float2bfloat16(l0);
                __nv_bfloat16 g1 = __float2bfloat16(l1);
                uh[i] = (unsigned)__bfloat16_as_ushort(h0) | ((unsigned)__bfloat16_as_ushort(h1) << 16);
                ul[i] = (unsigned)__bfloat16_as_ushort(g0) | ((unsigned)__bfloat16_as_ushort(g1) << 16);
            }
            *(uint4*)&As_h[srow][skoff] = make_uint4(uh[0], uh[1], uh[2], uh[3]);
            *(uint4*)&As_l[srow][skoff] = make_uint4(ul[0], ul[1], ul[2], ul[3]);
        }
        // ---- stage B chunk (pre-split bf16, [n][k] global)
        {
            const __nv_bfloat16* src = (doBl ? Bl : Bh) + (size_t)(col0 + bn) * KTOT + kt + bhalf;
            uint4 v = *(const uint4*)src;
            if (doBl) *(uint4*)&Bs_l[bn][bhalf] = v;
            else      *(uint4*)&Bs_h[bn][bhalf] = v;
        }
        __syncthreads();

        // ---- fragments + MMAs
        unsigned Ah[4], Al[4];
        int mr = warp * 16;
        Ah[0] = *(const unsigned*)&As_h[mr + g][q];
        Ah[1] = *(const unsigned*)&As_h[mr + g + 8][q];
        Ah[2] = *(const unsigned*)&As_h[mr + g][q + 8];
        Ah[3] = *(const unsigned*)&As_h[mr + g + 8][q + 8];
        Al[0] = *(const unsigned*)&As_l[mr + g][q];
        Al[1] = *(const unsigned*)&As_l[mr + g + 8][q];
        Al[2] = *(const unsigned*)&As_l[mr + g][q + 8];
        Al[3] = *(const unsigned*)&As_l[mr + g + 8][q + 8];
#pragma unroll
        for (int nt = 0; nt < 8; nt++) {
            unsigned bh[2], bl[2];
            bh[0] = *(const unsigned*)&Bs_h[nt * 8 + g][q];
            bh[1] = *(const unsigned*)&Bs_h[nt * 8 + g][q + 8];
            bl[0] = *(const unsigned*)&Bs_l[nt * 8 + g][q];
            bl[1] = *(const unsigned*)&Bs_l[nt * 8 + g][q + 8];
            mma_bf16(acc[nt], Ah, bh);
            mma_bf16(acc[nt], Al, bh);
            mma_bf16(acc[nt], Ah, bl);
        }
        __syncthreads();
    }

    // ---- fused epilogues (C frag: rows r0=w*16+g, r1=r0+8; cols nt*8+q, +1)
    int r0 = row0 + warp * 16 + g;
    int r1 = r0 + 8;
    float fA[6] = {0, 0, 0, 0, 0, 0}, fB[6] = {0, 0, 0, 0, 0, 0};
    if (MODE == 1 || MODE == 2) {
        if (r0 < M) {
            const float* f = g_f + (size_t)r0 * 6;
            fA[0] = f[0]; fA[1] = f[1]; fA[2] = f[2]; fA[3] = f[3]; fA[4] = f[4]; fA[5] = f[5];
        }
        if (r1 < M) {
            const float* f = g_f + (size_t)r1 * 6;
            fB[0] = f[0]; fB[1] = f[1]; fB[2] = f[2]; fB[3] = f[3]; fB[4] = f[4]; fB[5] = f[5];
        }
    }
#pragma unroll
    for (int nt = 0; nt < 8; nt++) {
        int c = col0 + nt * 8 + q;
#pragma unroll
        for (int half = 0; half < 2; half++) {
            int   row = half ? r1 : r0;
            float v0  = acc[nt][half * 2 + 0];
            float v1  = acc[nt][half * 2 + 1];
            const float* fv = half ? fB : fA;
            if (row >= M) continue;
            if (MODE == 0) {
                float2 o = make_float2(v0 + biasExt[c], v1 + biasExt[c + 1]);
                *(float2*)&g_hc[(size_t)row * 128 + c] = o;
            } else if (MODE == 3) {
                float2* p = (float2*)&g_hc[(size_t)row * 128 + c];
                float2 o = *p; o.x += v0; o.y += v1; *p = o;
            } else if (MODE == 1) {
                float w0 = v0 + g_biaszr[c]
                         + fv[0] * g_M6zr[c]          + fv[1] * g_M6zr[256 + c]
                         + fv[2] * g_M6zr[512 + c]    + fv[3] * g_M6zr[768 + c]
                         + fv[4] * g_M6zr[1024 + c]   + fv[5] * g_M6zr[1280 + c];
                float w1 = v1 + g_biaszr[c + 1]
                         + fv[0] * g_M6zr[c + 1]      + fv[1] * g_M6zr[257 + c]
                         + fv[2] * g_M6zr[513 + c]    + fv[3] * g_M6zr[769 + c]
                         + fv[4] * g_M6zr[1025 + c]   + fv[5] * g_M6zr[1281 + c];
                float2 o = make_float2(1.f / (1.f + expf(-w0)), 1.f / (1.f + expf(-w1)));
                *(float2*)&g_zr[(size_t)row * 256 + c] = o;
            } else {  // MODE 2
                float w0 = v0 + g_biasc[c]
                         + fv[0] * g_M6c[c]         + fv[1] * g_M6c[128 + c]
                         + fv[2] * g_M6c[256 + c]   + fv[3] * g_M6c[384 + c]
                         + fv[4] * g_M6c[512 + c]   + fv[5] * g_M6c[640 + c];
                float w1 = v1 + g_biasc[c + 1]
                         + fv[0] * g_M6c[c + 1]     + fv[1] * g_M6c[129 + c]
                         + fv[2] * g_M6c[257 + c]   + fv[3] * g_M6c[385 + c]
                         + fv[4] * g_M6c[513 + c]   + fv[5] * g_M6c[641 + c];
                float2 zp = *(const float2*)&g_zr[(size_t)row * 256 + c];
                float2 hp = *(const float2*)&g_h[(size_t)row * 128 + c];
                float2 o;
                o.x = zp.x * hp.x + (1.f - zp.x) * tanhf(w0);
                o.y = zp.y * hp.y + (1.f - zp.y) * tanhf(w1);
                *(float2*)&g_h[(size_t)row * 128 + c] = o;
            }
        }
    }
}

// ---------------- output head ----------------
__global__ void out_kernel(const float* __restrict__ Wo, const float* __restrict__ bo,
                           float* __restrict__ out) {
    int idx = blockIdx.x * blockDim.x + threadIdx.x;
    if (idx >= NTOT * HORZ) return;
    int i = idx / HORZ, hor = idx - i * HORZ;
    const float* hr = g_h + (size_t)i * HD;
    float s = bo[hor];
#pragma unroll 8
    for (int k = 0; k < HD; k++) s = fmaf(hr[k], Wo[k * HORZ + hor], s);
    int b = i / NNODE, n = i - b * NNODE;
    out[(size_t)(b * HORZ + hor) * NNODE + n] = s;
}

// ---------------- launch ----------------
extern "C" void kernel_launch(void* const* d_in, const int* in_sizes, int n_in,
                              void* d_out, int out_size) {
    const float* x  = (const float*)d_in[0];
    const void*  ei = d_in[1];
    const float* W1 = (const float*)d_in[2];
    const float* b1 = (const float*)d_in[3];
    const float* W2 = (const float*)d_in[4];
    const float* b2 = (const float*)d_in[5];
    const float* Wz = (const float*)d_in[6];
    const float* bz = (const float*)d_in[7];
    const float* Wr = (const float*)d_in[8];
    const float* br = (const float*)d_in[9];
    const float* Wc = (const float*)d_in[10];
    const float* bc = (const float*)d_in[11];
    const float* Wo = (const float*)d_in[12];
    const float* bo = (const float*)d_in[13];
    float* out = (float*)d_out;
    (void)in_sizes; (void)n_in; (void)out_size;

    // setup
    zero_h_kernel<<<(NTOT * HD + 1023) / 1024, 1024>>>();
    zero_counts_kernel<<<(2 * NNODE + 255) / 256, 256>>>();
    detect_dtype_kernel<<<(2 * NEDGE + 255) / 256, 256>>>(ei);
    set_is64_kernel<<<1, 1>>>();
    count_edges_kernel<<<(NEDGE + 255) / 256, 256>>>(ei);
    norm_kernel<<<(NEDGE + 255) / 256, 256>>>(ei);
    scan_kernel<<<1, 1024>>>();
    fill_kernel<<<(NEDGE + 255) / 256, 256>>>(ei);
    build_bsplit_kernel<<<(98304 + 255) / 256, 256>>>(W2, Wz, Wr, Wc);
    build_zr_fold_kernel<<<(7 * 256 + 255) / 256, 256>>>(W1, b1, Wz, bz, Wr, br);
    build_c_fold_kernel<<<(7 * HD + 255) / 256, 256>>>(W1, b1, Wc, bc);

    const int MB = NTOT / 128;   // 1250
    const int MB3 = (NNODE + 127) / 128;  // 40
    for (int t = 0; t < TSTEPS; t++) {
        const float* xt0 = x + (size_t)t * NNODE * INF;   // batch 0, timestep t
        prop2_kernel<<<(NNODE * INF + 127) / 128, 128>>>(xt0, 0);
        prop2_kernel<<<(NNODE * INF + 127) / 128, 128>>>(xt0, 1);
        prop128_kernel<<<NNODE, HD>>>(0);
        prop128_kernel<<<NNODE, HD>>>(1);
        build_f_kernel<<<(NTOT + 255) / 256, 256>>>(x, t);

        // hc = h @ (W2[0]-W2[2])^T? (transposed-weight GEMM) + b2
        mma_gemm<0, 128><<<dim3(2, MB), 256>>>(b2, NTOT);
        // hc[0:5000] += P1@W2[1] + 2*P2@W2[2]
        mma_gemm<3, 256><<<dim3(2, MB3), 256>>>(nullptr, NNODE);
        // zr = sigmoid(hc @ Wzr_bot + f@M6zr + biaszr)
        mma_gemm<1, 128><<<dim3(4, MB), 256>>>(nullptr, NTOT);
        // h = z*h + (1-z)*tanh((r.*hc) @ Wc_bot + f@M6c + biasc)
        mma_gemm<2, 128><<<dim3(2, MB), 256>>>(nullptr, NTOT);
    }

    out_kernel<<<(NTOT * HORZ + 255) / 256, 256>>>(Wo, bo, out);
}

// round 9
// speedup vs baseline: 2.1690x; 1.1082x over previous
#include <cuda_runtime.h>
#include <cuda_fp16.h>
#include <math.h>
#include <cstdint>

#define NTOT   160000
#define NNODE  5000
#define NEDGE  80000
#define TSTEPS 12
#define HD     128
#define HORZ   12
#define INF    2

// ---------------- static device scratch ----------------
__device__ float g_h   [NTOT * HD];
__device__ float g_hc  [NTOT * HD];
__device__ float g_zr  [NTOT * 2 * HD];
__device__ float g_f   [NTOT * 6];
__device__ float g_P1  [NNODE * HD];
__device__ float g_P2  [NNODE * HD];
__device__ float g_X1  [NNODE * INF];
__device__ float g_X2  [NNODE * INF];
__device__ float g_norm[NEDGE];
__device__ int   g_degsrc[NNODE];
__device__ int   g_cnt [NNODE];
__device__ int   g_off [NNODE + 1];
__device__ int   g_cur [NNODE];
__device__ int   g_csrsrc[NEDGE];
__device__ float g_csrw  [NEDGE];
__device__ float g_M6zr  [6 * 2 * HD];
__device__ float g_biaszr[2 * HD];
__device__ float g_M6c   [6 * HD];
__device__ float g_biasc [HD];
__device__ int   g_bad64;
__device__ int   g_is64;

// fp16 transposed weights [n][k], built once per launch
__device__ __align__(16) __half g_A2t [128 * 128];   // W2[0]-W2[2]
__device__ __align__(16) __half g_W2bt[128 * 256];   // [W2[1]; 2*W2[2]] stacked-K
__device__ __align__(16) __half g_Wzrt[256 * 128];   // bottom [Wz|Wr]
__device__ __align__(16) __half g_Wct [128 * 128];   // bottom Wc

// ---------------- warp-MMA primitives ----------------
__device__ __forceinline__ uint32_t smem_u32(const void* p) {
    uint32_t a;
    asm("{ .reg .u64 t; cvta.to.shared.u64 t, %1; cvt.u32.u64 %0, t; }" : "=r"(a) : "l"(p));
    return a;
}
__device__ __forceinline__ void ldsm_x4(uint32_t* r, uint32_t addr) {
    asm volatile("ldmatrix.sync.aligned.m8n8.x4.shared.b16 {%0,%1,%2,%3}, [%4];"
        : "=r"(r[0]), "=r"(r[1]), "=r"(r[2]), "=r"(r[3]) : "r"(addr));
}
__device__ __forceinline__ void mma_f16(float* c, const uint32_t* a, const uint32_t* b) {
    asm volatile("mma.sync.aligned.m16n8k16.row.col.f32.f16.f16.f32 "
        "{%0,%1,%2,%3}, {%4,%5,%6,%7}, {%8,%9}, {%0,%1,%2,%3};"
        : "+f"(c[0]), "+f"(c[1]), "+f"(c[2]), "+f"(c[3])
        : "r"(a[0]), "r"(a[1]), "r"(a[2]), "r"(a[3]), "r"(b[0]), "r"(b[1]));
}

// ---------------- edge dtype probe ----------------
__global__ void detect_dtype_kernel(const void* __restrict__ ei) {
    int e = blockIdx.x * blockDim.x + threadIdx.x;
    if (e >= 2 * NEDGE) return;
    long long v = ((const long long*)ei)[e];
    if (v < 0 || v >= NNODE) atomicOr(&g_bad64, 1);
}
__global__ void set_is64_kernel() { g_is64 = g_bad64 ? 0 : 1; }

__device__ __forceinline__ int edge_at(const void* __restrict__ ei, int idx) {
    int s;
    if (g_is64) s = (int)((const long long*)ei)[idx];
    else        s = ((const int*)ei)[idx];
    if (s < 0) s = 0;
    if (s >= NNODE) s = NNODE - 1;
    return s;
}

// ---------------- setup kernels ----------------
__global__ void zero_h_kernel() {
    int i = blockIdx.x * blockDim.x + threadIdx.x;
    if (i < NTOT * HD) g_h[i] = 0.f;
}
__global__ void zero_counts_kernel() {
    int i = blockIdx.x * blockDim.x + threadIdx.x;
    if (i < NNODE) g_degsrc[i] = 0;
    else if (i < 2 * NNODE) g_cnt[i - NNODE] = 0;
    if (i == 0) g_bad64 = 0;
}
__global__ void count_edges_kernel(const void* __restrict__ ei) {
    int e = blockIdx.x * blockDim.x + threadIdx.x;
    if (e >= NEDGE) return;
    atomicAdd(&g_degsrc[edge_at(ei, e)], 1);
    atomicAdd(&g_cnt[edge_at(ei, NEDGE + e)], 1);
}
__global__ void norm_kernel(const void* __restrict__ ei) {
    int e = blockIdx.x * blockDim.x + threadIdx.x;
    if (e >= NEDGE) return;
    int s = edge_at(ei, e), d = edge_at(ei, NEDGE + e);
    int ds = g_degsrc[s], dd = g_degsrc[d];
    float is = (ds > 0) ? rsqrtf((float)ds) : 0.f;
    float id = (dd > 0) ? rsqrtf((float)dd) : 0.f;
    g_norm[e] = -is * id;
}
__global__ void scan_kernel() {
    __shared__ int sh[1024];
    int t = threadIdx.x;
    int start = t * 5, end = start + 5;
    if (end > NNODE) end = NNODE;
    int s = 0;
    for (int i = start; i < end && i < NNODE; i++) s += g_cnt[i];
    sh[t] = s;
    __syncthreads();
    for (int off = 1; off < 1024; off <<= 1) {
        int v = (t >= off) ? sh[t - off] : 0;
        __syncthreads();
        sh[t] += v;
        __syncthreads();
    }
    int run = (t == 0) ? 0 : sh[t - 1];
    for (int i = start; i < end && i < NNODE; i++) {
        g_off[i] = run; g_cur[i] = run; run += g_cnt[i];
    }
    if (t == 1023) g_off[NNODE] = sh[1023];
}
__global__ void fill_kernel(const void* __restrict__ ei) {
    int e = blockIdx.x * blockDim.x + threadIdx.x;
    if (e >= NEDGE) return;
    int s = edge_at(ei, e), d = edge_at(ei, NEDGE + e);
    int p = atomicAdd(&g_cur[d], 1);
    if (p >= NEDGE) p = NEDGE - 1;
    g_csrsrc[p] = s;
    g_csrw[p]   = g_norm[e];
}

__global__ void build_bhalf_kernel(const float* __restrict__ W2, const float* __restrict__ Wz,
                                   const float* __restrict__ Wr, const float* __restrict__ Wc) {
    int i = blockIdx.x * blockDim.x + threadIdx.x;
    if (i < 16384) {
        int n = i >> 7, k = i & 127;
        g_A2t[n * 128 + k] = __float2half_rn(W2[k * 128 + n] - W2[2 * 16384 + k * 128 + n]);
    } else if (i < 49152) {
        int j = i - 16384; int n = j >> 8, k = j & 255;
        float v = (k < 128) ? W2[16384 + k * 128 + n] : 2.f * W2[32768 + (k - 128) * 128 + n];
        g_W2bt[n * 256 + k] = __float2half_rn(v);
    } else if (i < 81920) {
        int j = i - 49152; int n = j >> 7, k = j & 127;
        float v = (n < 128) ? Wz[(128 + k) * 128 + n] : Wr[(128 + k) * 128 + (n - 128)];
        g_Wzrt[n * 128 + k] = __float2half_rn(v);
    } else if (i < 98304) {
        int j = i - 81920; int n = j >> 7, k = j & 127;
        g_Wct[n * 128 + k] = __float2half_rn(Wc[(128 + k) * 128 + n]);
    }
}

__device__ __forceinline__ float ic_row_elem(const float* W1, const float* b1, int r, int k) {
    switch (r) {
        case 0: return W1[k]        - W1[512 + k];
        case 1: return W1[128 + k]  - W1[640 + k];
        case 2: return W1[256 + k];
        case 3: return W1[384 + k];
        case 4: return 2.f * W1[512 + k];
        case 5: return 2.f * W1[640 + k];
        default: return b1[k];
    }
}
__global__ void build_zr_fold_kernel(const float* __restrict__ W1, const float* __restrict__ b1,
                                     const float* __restrict__ Wz, const float* __restrict__ bz,
                                     const float* __restrict__ Wr, const float* __restrict__ br) {
    int idx = blockIdx.x * blockDim.x + threadIdx.x;
    if (idx >= 7 * 256) return;
    int r = idx / 256, j = idx % 256;
    const float* Wtop = (j < HD) ? Wz : Wr;
    int jj = j & (HD - 1);
    float s = 0.f;
    for (int k = 0; k < HD; k++) s += ic_row_elem(W1, b1, r, k) * Wtop[k * HD + jj];
    if (r < 6) g_M6zr[r * 256 + j] = s;
    else       g_biaszr[j] = s + ((j < HD) ? bz[jj] : br[jj]);
}
__global__ void build_c_fold_kernel(const float* __restrict__ W1, const float* __restrict__ b1,
                                    const float* __restrict__ Wc, const float* __restrict__ bc) {
    int idx = blockIdx.x * blockDim.x + threadIdx.x;
    if (idx >= 7 * HD) return;
    int r = idx / HD, j = idx % HD;
    float s = 0.f;
    for (int k = 0; k < HD; k++) s += ic_row_elem(W1, b1, r, k) * Wc[k * HD + j];
    if (r < 6) g_M6c[r * HD + j] = s;
    else       g_biasc[j] = s + bc[j];
}

// ---------------- graph propagation ----------------
__global__ void prop128_kernel(int sel) {
    const float* tin  = sel ? g_P1 : g_h;
    float*       tout = sel ? g_P2 : g_P1;
    int d = blockIdx.x, j = threadIdx.x;
    int p0 = g_off[d], p1 = g_off[d + 1];
    float acc = 0.f;
    for (int p = p0; p < p1; p++)
        acc = fmaf(g_csrw[p], tin[g_csrsrc[p] * HD + j], acc);
    tout[d * HD + j] = acc;
}
__global__ void prop2_kernel(const float* __restrict__ xin, int sel) {
    int idx = blockIdx.x * blockDim.x + threadIdx.x;
    if (idx >= NNODE * INF) return;
    int d = idx >> 1, c = idx & 1;
    const float* tin  = sel ? g_X1 : xin;
    float*       tout = sel ? g_X2 : g_X1;
    int p0 = g_off[d], p1 = g_off[d + 1];
    float acc = 0.f;
    for (int p = p0; p < p1; p++)
        acc = fmaf(g_csrw[p], tin[g_csrsrc[p] * INF + c], acc);
    tout[idx] = acc;
}
__global__ void build_f_kernel(const float* __restrict__ x, int t) {
    int i = blockIdx.x * blockDim.x + threadIdx.x;
    if (i >= NTOT) return;
    int b = i / NNODE, n = i - b * NNODE;
    const float* xr = x + ((size_t)(b * TSTEPS + t) * NNODE + n) * INF;
    float* f = g_f + (size_t)i * 6;
    f[0] = xr[0]; f[1] = xr[1];
    if (i < NNODE) {
        f[2] = g_X1[i * 2]; f[3] = g_X1[i * 2 + 1];
        f[4] = g_X2[i * 2]; f[5] = g_X2[i * 2 + 1];
    } else {
        f[2] = 0.f; f[3] = 0.f; f[4] = 0.f; f[5] = 0.f;
    }
}

// ---------------- fused split-fp16 HMMA GEMM ----------------
// A split a_h+a_l fp16 staged once per block; B fp16 (weights) staged per 64-col chunk.
// MODE 0: hc = h @ A2t^T + b2            (K=128, NCOL=128)
// MODE 3: hc += [P1|P2] @ W2bt^T         (K=256, NCOL=128, x2 folded)
// MODE 1: zr = sigmoid(hc @ Wzrt^T + rank6 + bias)   (K=128, NCOL=256)
// MODE 2: h  = z*h + (1-z)*tanh((r.*hc) @ Wct^T + rank6 + bias)
template <int MODE>
__global__ __launch_bounds__(256)
void hmma_gemm(const float* __restrict__ biasExt, int M) {
    constexpr int K    = (MODE == 3) ? 256 : 128;
    constexpr int KP   = K + 8;                 // padded row (halves) for conflict-free LDSM
    constexpr int NCOL = (MODE == 1) ? 256 : 128;
    constexpr int NCH  = NCOL / 64;

    extern __shared__ __align__(16) char sm[];
    __half* Ah_s = (__half*)sm;                 // [128][KP]
    __half* Al_s = Ah_s + 128 * KP;
    __half* B_s  = Al_s + 128 * KP;             // [64][KP]

    int tid = threadIdx.x, lane = tid & 31, w = tid >> 5;
    int row0 = blockIdx.y * 128;

    // ---- stage A once: fp32 -> (a_h, a_l) fp16
    {
        int r  = tid >> 1;
        int kb = (tid & 1) * (K / 2);
        int gr = row0 + r;
#pragma unroll
        for (int kk = 0; kk < K / 2; kk += 8) {
            int k0 = kb + kk;
            float a[8];
            if (gr < M) {
                const float* src;
                if (MODE == 3)      src = (k0 < 128) ? (g_P1 + (size_t)gr * 128 + k0)
                                                     : (g_P2 + (size_t)gr * 128 + (k0 - 128));
                else if (MODE == 0) src = g_h  + (size_t)gr * 128 + k0;
                else                src = g_hc + (size_t)gr * 128 + k0;
                float4 v0 = *(const float4*)(src);
                float4 v1 = *(const float4*)(src + 4);
                if (MODE == 2) {
                    const float* rp = g_zr + (size_t)gr * 256 + 128 + k0;
                    float4 r0 = *(const float4*)(rp);
                    float4 r1 = *(const float4*)(rp + 4);
                    v0.x *= r0.x; v0.y *= r0.y; v0.z *= r0.z; v0.w *= r0.w;
                    v1.x *= r1.x; v1.y *= r1.y; v1.z *= r1.z; v1.w *= r1.w;
                }
                a[0] = v0.x; a[1] = v0.y; a[2] = v0.z; a[3] = v0.w;
                a[4] = v1.x; a[5] = v1.y; a[6] = v1.z; a[7] = v1.w;
            } else {
#pragma unroll
                for (int i = 0; i < 8; i++) a[i] = 0.f;
            }
            uint32_t hw[4], lw[4];
#pragma unroll
            for (int i = 0; i < 4; i++) {
                __half h0 = __float2half_rn(a[2 * i]);
                __half h1 = __float2half_rn(a[2 * i + 1]);
                __half l0 = __float2half_rn(a[2 * i]     - __half2float(h0));
                __half l1 = __float2half_rn(a[2 * i + 1] - __half2float(h1));
                hw[i] = (uint32_t)__half_as_ushort(h0) | ((uint32_t)__half_as_ushort(h1) << 16);
                lw[i] = (uint32_t)__half_as_ushort(l0) | ((uint32_t)__half_as_ushort(l1) << 16);
            }
            *(uint4*)&Ah_s[r * KP + k0] = make_uint4(hw[0], hw[1], hw[2], hw[3]);
            *(uint4*)&Al_s[r * KP + k0] = make_uint4(lw[0], lw[1], lw[2], lw[3]);
        }
    }
    __syncthreads();

    // ldmatrix lane base addresses
    uint32_t aBase = smem_u32(Ah_s) + ((uint32_t)((w * 16 + (lane & 15)) * KP + ((lane >> 4) << 3)) << 1);
    const uint32_t aLoOff = (uint32_t)(128 * KP * 2);
    uint32_t bBase = smem_u32(B_s) + ((uint32_t)(((lane & 7) + ((lane & 16) >> 1)) * KP) << 1) + ((lane & 8) << 1);

    int g = lane >> 2, q = (lane & 3) << 1;
    const __half* Bw;
    if (MODE == 0)      Bw = g_A2t;
    else if (MODE == 3) Bw = g_W2bt;
    else if (MODE == 1) Bw = g_Wzrt;
    else                Bw = g_Wct;

    for (int ch = 0; ch < NCH; ch++) {
        // ---- stage B chunk [64][K]
        {
            const __half* Bg = Bw + (size_t)(ch * 64) * K;
            constexpr int NV = 64 * K / 8;
            for (int i = tid; i < NV; i += 256) {
                int n = i / (K / 8), k8 = (i % (K / 8)) * 8;
                *(uint4*)&B_s[n * KP + k8] = *(const uint4*)(Bg + (size_t)n * K + k8);
            }
        }
        __syncthreads();

        float acc[8][4];
#pragma unroll
        for (int i = 0; i < 8; i++)
#pragma unroll
            for (int j = 0; j < 4; j++) acc[i][j] = 0.f;

#pragma unroll
        for (int kt = 0; kt < K / 16; kt++) {
            uint32_t Af[4], Alf[4];
            ldsm_x4(Af,  aBase + kt * 32);
            ldsm_x4(Alf, aBase + aLoOff + kt * 32);
#pragma unroll
            for (int p = 0; p < 4; p++) {
                uint32_t bf[4];
                ldsm_x4(bf, bBase + kt * 32 + p * (16 * KP * 2));
                mma_f16(acc[2 * p],     Af,  bf);
                mma_f16(acc[2 * p],     Alf, bf);
                mma_f16(acc[2 * p + 1], Af,  bf + 2);
                mma_f16(acc[2 * p + 1], Alf, bf + 2);
            }
        }

        // ---- fused epilogue for this chunk
        int r0 = row0 + w * 16 + g;
        int r1 = r0 + 8;
        float fA[6] = {0, 0, 0, 0, 0, 0}, fB[6] = {0, 0, 0, 0, 0, 0};
        if (MODE == 1 || MODE == 2) {
            if (r0 < M) {
                const float* f = g_f + (size_t)r0 * 6;
                fA[0]=f[0]; fA[1]=f[1]; fA[2]=f[2]; fA[3]=f[3]; fA[4]=f[4]; fA[5]=f[5];
            }
            if (r1 < M) {
                const float* f = g_f + (size_t)r1 * 6;
                fB[0]=f[0]; fB[1]=f[1]; fB[2]=f[2]; fB[3]=f[3]; fB[4]=f[4]; fB[5]=f[5];
            }
        }
#pragma unroll
        for (int nt = 0; nt < 8; nt++) {
            int c = ch * 64 + nt * 8 + q;
#pragma unroll
            for (int half = 0; half < 2; half++) {
                int   row = half ? r1 : r0;
                float v0  = acc[nt][half * 2 + 0];
                float v1  = acc[nt][half * 2 + 1];
                const float* fv = half ? fB : fA;
                if (row >= M) continue;
                if (MODE == 0) {
                    float2 o = make_float2(v0 + biasExt[c], v1 + biasExt[c + 1]);
                    *(float2*)&g_hc[(size_t)row * 128 + c] = o;
                } else if (MODE == 3) {
                    float2* p = (float2*)&g_hc[(size_t)row * 128 + c];
                    float2 o = *p; o.x += v0; o.y += v1; *p = o;
                } else if (MODE == 1) {
                    float w0 = v0 + g_biaszr[c]
                             + fv[0] * g_M6zr[c]          + fv[1] * g_M6zr[256 + c]
                             + fv[2] * g_M6zr[512 + c]    + fv[3] * g_M6zr[768 + c]
                             + fv[4] * g_M6zr[1024 + c]   + fv[5] * g_M6zr[1280 + c];
                    float w1 = v1 + g_biaszr[c + 1]
                             + fv[0] * g_M6zr[c + 1]      + fv[1] * g_M6zr[257 + c]
                             + fv[2] * g_M6zr[513 + c]    + fv[3] * g_M6zr[769 + c]
                             + fv[4] * g_M6zr[1025 + c]   + fv[5] * g_M6zr[1281 + c];
                    float2 o = make_float2(1.f / (1.f + expf(-w0)), 1.f / (1.f + expf(-w1)));
                    *(float2*)&g_zr[(size_t)row * 256 + c] = o;
                } else {  // MODE 2: fused GRU update
                    float w0 = v0 + g_biasc[c]
                             + fv[0] * g_M6c[c]         + fv[1] * g_M6c[128 + c]
                             + fv[2] * g_M6c[256 + c]   + fv[3] * g_M6c[384 + c]
                             + fv[4] * g_M6c[512 + c]   + fv[5] * g_M6c[640 + c];
                    float w1 = v1 + g_biasc[c + 1]
                             + fv[0] * g_M6c[c + 1]     + fv[1] * g_M6c[129 + c]
                             + fv[2] * g_M6c[257 + c]   + fv[3] * g_M6c[385 + c]
                             + fv[4] * g_M6c[513 + c]   + fv[5] * g_M6c[641 + c];
                    float2 zp = *(const float2*)&g_zr[(size_t)row * 256 + c];
                    float2 hp = *(const float2*)&g_h[(size_t)row * 128 + c];
                    float2 o;
                    o.x = zp.x * hp.x + (1.f - zp.x) * tanhf(w0);
                    o.y = zp.y * hp.y + (1.f - zp.y) * tanhf(w1);
                    *(float2*)&g_h[(size_t)row * 128 + c] = o;
                }
            }
        }
        __syncthreads();
    }
}

// ---------------- output head ----------------
__global__ void out_kernel(const float* __restrict__ Wo, const float* __restrict__ bo,
                           float* __restrict__ out) {
    int idx = blockIdx.x * blockDim.x + threadIdx.x;
    if (idx >= NTOT * HORZ) return;
    int i = idx / HORZ, hor = idx - i * HORZ;
    const float* hr = g_h + (size_t)i * HD;
    float s = bo[hor];
#pragma unroll 8
    for (int k = 0; k < HD; k++) s = fmaf(hr[k], Wo[k * HORZ + hor], s);
    int b = i / NNODE, n = i - b * NNODE;
    out[(size_t)(b * HORZ + hor) * NNODE + n] = s;
}

// ---------------- launch ----------------
extern "C" void kernel_launch(void* const* d_in, const int* in_sizes, int n_in,
                              void* d_out, int out_size) {
    const float* x  = (const float*)d_in[0];
    const void*  ei = d_in[1];
    const float* W1 = (const float*)d_in[2];
    const float* b1 = (const float*)d_in[3];
    const float* W2 = (const float*)d_in[4];
    const float* b2 = (const float*)d_in[5];
    const float* Wz = (const float*)d_in[6];
    const float* bz = (const float*)d_in[7];
    const float* Wr = (const float*)d_in[8];
    const float* br = (const float*)d_in[9];
    const float* Wc = (const float*)d_in[10];
    const float* bc = (const float*)d_in[11];
    const float* Wo = (const float*)d_in[12];
    const float* bo = (const float*)d_in[13];
    float* out = (float*)d_out;
    (void)in_sizes; (void)n_in; (void)out_size;

    // dynamic smem: A hi+lo [128][K+8] + B [64][K+8], fp16
    const int S128 = (2 * 128 * (128 + 8) + 64 * (128 + 8)) * 2;  //  87040
    const int S256 = (2 * 128 * (256 + 8) + 64 * (256 + 8)) * 2;  // 168960
    cudaFuncSetAttribute(hmma_gemm<0>, cudaFuncAttributeMaxDynamicSharedMemorySize, S128);
    cudaFuncSetAttribute(hmma_gemm<1>, cudaFuncAttributeMaxDynamicSharedMemorySize, S128);
    cudaFuncSetAttribute(hmma_gemm<2>, cudaFuncAttributeMaxDynamicSharedMemorySize, S128);
    cudaFuncSetAttribute(hmma_gemm<3>, cudaFuncAttributeMaxDynamicSharedMemorySize, S256);

    zero_h_kernel<<<(NTOT * HD + 1023) / 1024, 1024>>>();
    zero_counts_kernel<<<(2 * NNODE + 255) / 256, 256>>>();
    detect_dtype_kernel<<<(2 * NEDGE + 255) / 256, 256>>>(ei);
    set_is64_kernel<<<1, 1>>>();
    count_edges_kernel<<<(NEDGE + 255) / 256, 256>>>(ei);
    norm_kernel<<<(NEDGE + 255) / 256, 256>>>(ei);
    scan_kernel<<<1, 1024>>>();
    fill_kernel<<<(NEDGE + 255) / 256, 256>>>(ei);
    build_bhalf_kernel<<<(98304 + 255) / 256, 256>>>(W2, Wz, Wr, Wc);
    build_zr_fold_kernel<<<(7 * 256 + 255) / 256, 256>>>(W1, b1, Wz, bz, Wr, br);
    build_c_fold_kernel<<<(7 * HD + 255) / 256, 256>>>(W1, b1, Wc, bc);

    const int MB  = NTOT / 128;            // 1250
    const int MB3 = (NNODE + 127) / 128;   // 40
    for (int t = 0; t < TSTEPS; t++) {
        const float* xt0 = x + (size_t)t * NNODE * INF;   // batch 0, timestep t
        prop2_kernel<<<(NNODE * INF + 127) / 128, 128>>>(xt0, 0);
        prop2_kernel<<<(NNODE * INF + 127) / 128, 128>>>(xt0, 1);
        prop128_kernel<<<NNODE, HD>>>(0);
        prop128_kernel<<<NNODE, HD>>>(1);
        build_f_kernel<<<(NTOT + 255) / 256, 256>>>(x, t);

        hmma_gemm<0><<<dim3(1, MB),  256, S128>>>(b2, NTOT);       // hc = h@A2eff + b2
        hmma_gemm<3><<<dim3(1, MB3), 256, S256>>>(nullptr, NNODE); // hc[0:5000] += [P1|2P2]@W2b
        hmma_gemm<1><<<dim3(1, MB),  256, S128>>>(nullptr, NTOT);  // zr = sigmoid(...)
        hmma_gemm<2><<<dim3(1, MB),  256, S128>>>(nullptr, NTOT);  // h = GRU update
    }

    out_kernel<<<(NTOT * HORZ + 255) / 256, 256>>>(Wo, bo, out);
}

// round 10
// speedup vs baseline: 3.1137x; 1.4356x over previous
#include <cuda_runtime.h>
#include <cuda_fp16.h>
#include <math.h>
#include <cstdint>

#define NTOT   160000
#define NNODE  5000
#define NEDGE  80000
#define TSTEPS 12
#define HD     128
#define HORZ   12
#define INF    2

#define HKP 136   // half stride for K=128 tiles
#define AKP 264   // half stride for K=256 tiles
#define ZKP 132   // float stride for z tile

// ---------------- static device scratch ----------------
__device__ float g_h   [NTOT * HD];
__device__ float g_P1  [NNODE * HD];
__device__ float g_P2  [NNODE * HD];
__device__ float g_X1  [NNODE * INF];
__device__ float g_X2  [NNODE * INF];
__device__ float g_norm[NEDGE];
__device__ int   g_degsrc[NNODE];
__device__ int   g_cnt [NNODE];
__device__ int   g_off [NNODE + 1];
__device__ int   g_cur [NNODE];
__device__ int   g_csrsrc[NEDGE];
__device__ float g_csrw  [NEDGE];
__device__ float g_M6zr  [6 * 2 * HD];
__device__ float g_biaszr[2 * HD];
__device__ float g_M6c   [6 * HD];
__device__ float g_biasc [HD];
__device__ int   g_bad64;
__device__ int   g_is64;

// fp16 transposed weights [n][k]
__device__ __align__(16) __half g_A2t [128 * 128];   // W2[0]-W2[2]
__device__ __align__(16) __half g_W2bt[128 * 256];   // [W2[1]; 2*W2[2]] stacked-K
__device__ __align__(16) __half g_Wzrt[256 * 128];   // bottom [Wz|Wr]
__device__ __align__(16) __half g_Wct [128 * 128];   // bottom Wc

// ---------------- warp-MMA primitives ----------------
__device__ __forceinline__ uint32_t smem_u32(const void* p) {
    uint32_t a;
    asm("{ .reg .u64 t; cvta.to.shared.u64 t, %1; cvt.u32.u64 %0, t; }" : "=r"(a) : "l"(p));
    return a;
}
__device__ __forceinline__ void ldsm_x4(uint32_t* r, uint32_t addr) {
    asm volatile("ldmatrix.sync.aligned.m8n8.x4.shared.b16 {%0,%1,%2,%3}, [%4];"
        : "=r"(r[0]), "=r"(r[1]), "=r"(r[2]), "=r"(r[3]) : "r"(addr));
}
__device__ __forceinline__ void mma_f16(float* c, const uint32_t* a, const uint32_t* b) {
    asm volatile("mma.sync.aligned.m16n8k16.row.col.f32.f16.f16.f32 "
        "{%0,%1,%2,%3}, {%4,%5,%6,%7}, {%8,%9}, {%0,%1,%2,%3};"
        : "+f"(c[0]), "+f"(c[1]), "+f"(c[2]), "+f"(c[3])
        : "r"(a[0]), "r"(a[1]), "r"(a[2]), "r"(a[3]), "r"(b[0]), "r"(b[1]));
}
__device__ __forceinline__ uint4 cvt8h(const float* a) {
    uint32_t u[4];
#pragma unroll
    for (int i = 0; i < 4; i++) {
        __half h0 = __float2half_rn(a[2 * i]);
        __half h1 = __float2half_rn(a[2 * i + 1]);
        u[i] = (uint32_t)__half_as_ushort(h0) | ((uint32_t)__half_as_ushort(h1) << 16);
    }
    return make_uint4(u[0], u[1], u[2], u[3]);
}

// ---------------- edge dtype probe ----------------
__global__ void detect_dtype_kernel(const void* __restrict__ ei) {
    int e = blockIdx.x * blockDim.x + threadIdx.x;
    if (e >= 2 * NEDGE) return;
    long long v = ((const long long*)ei)[e];
    if (v < 0 || v >= NNODE) atomicOr(&g_bad64, 1);
}
__global__ void set_is64_kernel() { g_is64 = g_bad64 ? 0 : 1; }

__device__ __forceinline__ int edge_at(const void* __restrict__ ei, int idx) {
    int s;
    if (g_is64) s = (int)((const long long*)ei)[idx];
    else        s = ((const int*)ei)[idx];
    if (s < 0) s = 0;
    if (s >= NNODE) s = NNODE - 1;
    return s;
}

// ---------------- setup kernels ----------------
__global__ void zero_h_kernel() {
    int i = blockIdx.x * blockDim.x + threadIdx.x;
    if (i < NTOT * HD) g_h[i] = 0.f;
}
__global__ void zero_counts_kernel() {
    int i = blockIdx.x * blockDim.x + threadIdx.x;
    if (i < NNODE) g_degsrc[i] = 0;
    else if (i < 2 * NNODE) g_cnt[i - NNODE] = 0;
    if (i == 0) g_bad64 = 0;
}
__global__ void count_edges_kernel(const void* __restrict__ ei) {
    int e = blockIdx.x * blockDim.x + threadIdx.x;
    if (e >= NEDGE) return;
    atomicAdd(&g_degsrc[edge_at(ei, e)], 1);
    atomicAdd(&g_cnt[edge_at(ei, NEDGE + e)], 1);
}
__global__ void norm_kernel(const void* __restrict__ ei) {
    int e = blockIdx.x * blockDim.x + threadIdx.x;
    if (e >= NEDGE) return;
    int s = edge_at(ei, e), d = edge_at(ei, NEDGE + e);
    int ds = g_degsrc[s], dd = g_degsrc[d];
    float is = (ds > 0) ? rsqrtf((float)ds) : 0.f;
    float id = (dd > 0) ? rsqrtf((float)dd) : 0.f;
    g_norm[e] = -is * id;
}
__global__ void scan_kernel() {
    __shared__ int sh[1024];
    int t = threadIdx.x;
    int start = t * 5, end = start + 5;
    if (end > NNODE) end = NNODE;
    int s = 0;
    for (int i = start; i < end && i < NNODE; i++) s += g_cnt[i];
    sh[t] = s;
    __syncthreads();
    for (int off = 1; off < 1024; off <<= 1) {
        int v = (t >= off) ? sh[t - off] : 0;
        __syncthreads();
        sh[t] += v;
        __syncthreads();
    }
    int run = (t == 0) ? 0 : sh[t - 1];
    for (int i = start; i < end && i < NNODE; i++) {
        g_off[i] = run; g_cur[i] = run; run += g_cnt[i];
    }
    if (t == 1023) g_off[NNODE] = sh[1023];
}
__global__ void fill_kernel(const void* __restrict__ ei) {
    int e = blockIdx.x * blockDim.x + threadIdx.x;
    if (e >= NEDGE) return;
    int s = edge_at(ei, e), d = edge_at(ei, NEDGE + e);
    int p = atomicAdd(&g_cur[d], 1);
    if (p >= NEDGE) p = NEDGE - 1;
    g_csrsrc[p] = s;
    g_csrw[p]   = g_norm[e];
}

__global__ void build_bhalf_kernel(const float* __restrict__ W2, const float* __restrict__ Wz,
                                   const float* __restrict__ Wr, const float* __restrict__ Wc) {
    int i = blockIdx.x * blockDim.x + threadIdx.x;
    if (i < 16384) {
        int n = i >> 7, k = i & 127;
        g_A2t[n * 128 + k] = __float2half_rn(W2[k * 128 + n] - W2[2 * 16384 + k * 128 + n]);
    } else if (i < 49152) {
        int j = i - 16384; int n = j >> 8, k = j & 255;
        float v = (k < 128) ? W2[16384 + k * 128 + n] : 2.f * W2[32768 + (k - 128) * 128 + n];
        g_W2bt[n * 256 + k] = __float2half_rn(v);
    } else if (i < 81920) {
        int j = i - 49152; int n = j >> 7, k = j & 127;
        float v = (n < 128) ? Wz[(128 + k) * 128 + n] : Wr[(128 + k) * 128 + (n - 128)];
        g_Wzrt[n * 128 + k] = __float2half_rn(v);
    } else if (i < 98304) {
        int j = i - 81920; int n = j >> 7, k = j & 127;
        g_Wct[n * 128 + k] = __float2half_rn(Wc[(128 + k) * 128 + n]);
    }
}

__device__ __forceinline__ float ic_row_elem(const float* W1, const float* b1, int r, int k) {
    switch (r) {
        case 0: return W1[k]        - W1[512 + k];
        case 1: return W1[128 + k]  - W1[640 + k];
        case 2: return W1[256 + k];
        case 3: return W1[384 + k];
        case 4: return 2.f * W1[512 + k];
        case 5: return 2.f * W1[640 + k];
        default: return b1[k];
    }
}
__global__ void build_zr_fold_kernel(const float* __restrict__ W1, const float* __restrict__ b1,
                                     const float* __restrict__ Wz, const float* __restrict__ bz,
                                     const float* __restrict__ Wr, const float* __restrict__ br) {
    int idx = blockIdx.x * blockDim.x + threadIdx.x;
    if (idx >= 7 * 256) return;
    int r = idx / 256, j = idx % 256;
    const float* Wtop = (j < HD) ? Wz : Wr;
    int jj = j & (HD - 1);
    float s = 0.f;
    for (int k = 0; k < HD; k++) s += ic_row_elem(W1, b1, r, k) * Wtop[k * HD + jj];
    if (r < 6) g_M6zr[r * 256 + j] = s;
    else       g_biaszr[j] = s + ((j < HD) ? bz[jj] : br[jj]);
}
__global__ void build_c_fold_kernel(const float* __restrict__ W1, const float* __restrict__ b1,
                                    const float* __restrict__ Wc, const float* __restrict__ bc) {
    int idx = blockIdx.x * blockDim.x + threadIdx.x;
    if (idx >= 7 * HD) return;
    int r = idx / HD, j = idx % HD;
    float s = 0.f;
    for (int k = 0; k < HD; k++) s += ic_row_elem(W1, b1, r, k) * Wc[k * HD + j];
    if (r < 6) g_M6c[r * HD + j] = s;
    else       g_biasc[j] = s + bc[j];
}

// ---------------- graph propagation ----------------
__global__ void prop128_kernel(int sel) {
    const float* tin  = sel ? g_P1 : g_h;
    float*       tout = sel ? g_P2 : g_P1;
    int d = blockIdx.x, j = threadIdx.x;
    int p0 = g_off[d], p1 = g_off[d + 1];
    float acc = 0.f;
    for (int p = p0; p < p1; p++)
        acc = fmaf(g_csrw[p], tin[g_csrsrc[p] * HD + j], acc);
    tout[d * HD + j] = acc;
}
__global__ void prop2_kernel(const float* __restrict__ xin, int sel) {
    int idx = blockIdx.x * blockDim.x + threadIdx.x;
    if (idx >= NNODE * INF) return;
    int d = idx >> 1, c = idx & 1;
    const float* tin  = sel ? g_X1 : xin;
    float*       tout = sel ? g_X2 : g_X1;
    int p0 = g_off[d], p1 = g_off[d + 1];
    float acc = 0.f;
    for (int p = p0; p < p1; p++)
        acc = fmaf(g_csrw[p], tin[g_csrsrc[p] * INF + c], acc);
    tout[idx] = acc;
}

// ---------------- fused TGCN cell: hc -> zr -> candidate -> h update ----------------
// smem layout (bytes): A 0..67584 | B 67584..102400 | r 102400..137216 | z 137216..204800
__global__ __launch_bounds__(256)
void cell_kernel(const float* __restrict__ x, int t, const float* __restrict__ b2) {
    extern __shared__ __align__(16) char sm[];
    __half* A_s = (__half*)sm;                     // [128][AKP] capable; HKP layout normally
    __half* B_s = (__half*)(sm + 67584);           // up to [128][HKP] or [64][AKP]
    __half* r_s = (__half*)(sm + 102400);          // [128][HKP]
    float*  z_s = (float*)(sm + 137216);           // [128][ZKP]

    int tid = threadIdx.x, lane = tid & 31, w = tid >> 5;
    int row0 = blockIdx.x * 128;
    bool corr = (row0 < NNODE);
    int g = lane >> 2, q = (lane & 3) << 1;
    int lr0 = w * 16 + g, lr1 = lr0 + 8;

    // rank-6 features for this thread's two rows
    float fA[6], fB[6];
    {
#pragma unroll
        for (int hh = 0; hh < 2; hh++) {
            int row = row0 + (hh ? lr1 : lr0);
            float* f = hh ? fB : fA;
            int b = row / NNODE, n = row - b * NNODE;
            const float* xr = x + ((size_t)(b * TSTEPS + t) * NNODE + n) * 2;
            f[0] = xr[0]; f[1] = xr[1];
            if (row < NNODE) {
                f[2] = g_X1[row * 2]; f[3] = g_X1[row * 2 + 1];
                f[4] = g_X2[row * 2]; f[5] = g_X2[row * 2 + 1];
            } else { f[2] = 0.f; f[3] = 0.f; f[4] = 0.f; f[5] = 0.f; }
        }
    }

    // ---- P0: stage h -> A_s (fp16, stride HKP) ; stage B <- A2t full
    {
        int rr = tid >> 1, kb = (tid & 1) << 6;
        const float* src = g_h + (size_t)(row0 + rr) * 128 + kb;
#pragma unroll
        for (int kk = 0; kk < 64; kk += 8) {
            float a[8];
            float4 v0 = *(const float4*)(src + kk);
            float4 v1 = *(const float4*)(src + kk + 4);
            a[0]=v0.x; a[1]=v0.y; a[2]=v0.z; a[3]=v0.w; a[4]=v1.x; a[5]=v1.y; a[6]=v1.z; a[7]=v1.w;
            *(uint4*)&A_s[rr * HKP + kb + kk] = cvt8h(a);
        }
    }
    for (int i = tid; i < 128 * 16; i += 256) {
        int n = i >> 4, k8 = (i & 15) << 3;
        *(uint4*)&B_s[n * HKP + k8] = *(const uint4*)&g_A2t[n * 128 + k8];
    }
    __syncthreads();

    uint32_t aB  = smem_u32(A_s) + ((uint32_t)((lr0 - g + (lane & 15)) * HKP + ((lane >> 4) << 3)) << 1);
    uint32_t bB  = smem_u32(B_s) + ((uint32_t)(((lane & 7) + ((lane & 16) >> 1)) * HKP) << 1) + ((lane & 8) << 1);

    // ---- GEMM1: hc = h @ A2t^T  (acc in fp32 frags)
    float hca[2][8][4];
#pragma unroll
    for (int c = 0; c < 2; c++)
#pragma unroll
        for (int i = 0; i < 8; i++)
#pragma unroll
            for (int j = 0; j < 4; j++) hca[c][i][j] = 0.f;

#pragma unroll
    for (int kt = 0; kt < 8; kt++) {
        uint32_t Af[4]; ldsm_x4(Af, aB + kt * 32);
#pragma unroll
        for (int ch = 0; ch < 2; ch++)
#pragma unroll
            for (int p = 0; p < 4; p++) {
                uint32_t bf[4];
                ldsm_x4(bf, bB + (uint32_t)(ch * 64 * HKP * 2) + kt * 32 + (uint32_t)(p * 16 * HKP * 2));
                mma_f16(hca[ch][2 * p],     Af, bf);
                mma_f16(hca[ch][2 * p + 1], Af, bf + 2);
            }
    }

    // ---- correction for rows < NNODE: hc += [P1|P2] @ W2bt^T (K=256, 2x folded)
    if (corr) {
        __syncthreads();
        {
            int rr = tid >> 1, kb = (tid & 1) << 7;
            int gr = row0 + rr;
#pragma unroll
            for (int kk = 0; kk < 128; kk += 8) {
                int k0 = kb + kk;
                float a[8];
                if (gr < NNODE) {
                    const float* s = (k0 < 128) ? g_P1 + (size_t)gr * 128 + k0
                                                : g_P2 + (size_t)gr * 128 + (k0 - 128);
                    float4 v0 = *(const float4*)(s);
                    float4 v1 = *(const float4*)(s + 4);
                    a[0]=v0.x; a[1]=v0.y; a[2]=v0.z; a[3]=v0.w; a[4]=v1.x; a[5]=v1.y; a[6]=v1.z; a[7]=v1.w;
                } else {
#pragma unroll
                    for (int i = 0; i < 8; i++) a[i] = 0.f;
                }
                *(uint4*)&A_s[rr * AKP + k0] = cvt8h(a);
            }
        }
        uint32_t aB2 = smem_u32(A_s) + ((uint32_t)((lr0 - g + (lane & 15)) * AKP + ((lane >> 4) << 3)) << 1);
        uint32_t bB2 = smem_u32(B_s) + ((uint32_t)(((lane & 7) + ((lane & 16) >> 1)) * AKP) << 1) + ((lane & 8) << 1);
        for (int ch = 0; ch < 2; ch++) {
            __syncthreads();
            for (int i = tid; i < 64 * 32; i += 256) {
                int n = i >> 5, k8 = (i & 31) << 3;
                *(uint4*)&B_s[n * AKP + k8] = *(const uint4*)&g_W2bt[(ch * 64 + n) * 256 + k8];
            }
            __syncthreads();
#pragma unroll
            for (int kt = 0; kt < 16; kt++) {
                uint32_t Af[4]; ldsm_x4(Af, aB2 + kt * 32);
#pragma unroll
                for (int p = 0; p < 4; p++) {
                    uint32_t bf[4];
                    ldsm_x4(bf, bB2 + kt * 32 + (uint32_t)(p * 16 * AKP * 2));
                    mma_f16(hca[ch][2 * p],     Af, bf);
                    mma_f16(hca[ch][2 * p + 1], Af, bf + 2);
                }
            }
        }
    }

    // ---- P3: hc + b2 -> A_s (fp16, stride HKP)
    __syncthreads();
#pragma unroll
    for (int ch = 0; ch < 2; ch++)
#pragma unroll
        for (int nt = 0; nt < 8; nt++) {
            int c = ch * 64 + nt * 8 + q;
            float b0 = b2[c], b1 = b2[c + 1];
            *(__half2*)&A_s[lr0 * HKP + c] = __floats2half2_rn(hca[ch][nt][0] + b0, hca[ch][nt][1] + b1);
            *(__half2*)&A_s[lr1 * HKP + c] = __floats2half2_rn(hca[ch][nt][2] + b0, hca[ch][nt][3] + b1);
        }
    __syncthreads();

    // ---- P4: GEMM2 zr = sigmoid(hc @ Wzrt^T + rank6 + bias) -> z_s fp32 / r_s fp16
    for (int half = 0; half < 2; half++) {
        if (half) __syncthreads();
        for (int i = tid; i < 128 * 16; i += 256) {
            int n = i >> 4, k8 = (i & 15) << 3;
            *(uint4*)&B_s[n * HKP + k8] = *(const uint4*)&g_Wzrt[(half * 128 + n) * 128 + k8];
        }
        __syncthreads();
#pragma unroll
        for (int ch = 0; ch < 2; ch++) {
            float acc[8][4];
#pragma unroll
            for (int i = 0; i < 8; i++)
#pragma unroll
                for (int j = 0; j < 4; j++) acc[i][j] = 0.f;
#pragma unroll
            for (int kt = 0; kt < 8; kt++) {
                uint32_t Af[4]; ldsm_x4(Af, aB + kt * 32);
#pragma unroll
                for (int p = 0; p < 4; p++) {
                    uint32_t bf[4];
                    ldsm_x4(bf, bB + (uint32_t)(ch * 64 * HKP * 2) + kt * 32 + (uint32_t)(p * 16 * HKP * 2));
                    mma_f16(acc[2 * p],     Af, bf);
                    mma_f16(acc[2 * p + 1], Af, bf + 2);
                }
            }
#pragma unroll
            for (int nt = 0; nt < 8; nt++) {
                int gc = half * 128 + ch * 64 + nt * 8 + q;
#pragma unroll
                for (int hh = 0; hh < 2; hh++) {
                    const float* fv = hh ? fB : fA;
                    int lrow = hh ? lr1 : lr0;
                    float v0 = acc[nt][hh * 2]     + g_biaszr[gc]
                             + fv[0] * g_M6zr[gc]        + fv[1] * g_M6zr[256 + gc]
                             + fv[2] * g_M6zr[512 + gc]  + fv[3] * g_M6zr[768 + gc]
                             + fv[4] * g_M6zr[1024 + gc] + fv[5] * g_M6zr[1280 + gc];
                    float v1 = acc[nt][hh * 2 + 1] + g_biaszr[gc + 1]
                             + fv[0] * g_M6zr[gc + 1]      + fv[1] * g_M6zr[257 + gc]
                             + fv[2] * g_M6zr[513 + gc]    + fv[3] * g_M6zr[769 + gc]
                             + fv[4] * g_M6zr[1025 + gc]   + fv[5] * g_M6zr[1281 + gc];
                    float s0 = 1.f / (1.f + expf(-v0));
                    float s1 = 1.f / (1.f + expf(-v1));
                    if (half == 0) *(float2*)&z_s[lrow * ZKP + gc] = make_float2(s0, s1);
                    else           *(__half2*)&r_s[lrow * HKP + (gc - 128)] = __floats2half2_rn(s0, s1);
                }
            }
        }
    }
    __syncthreads();

    // ---- P5: A_s *= r_s (in place), then stage B <- Wct
    for (int i = tid; i < 128 * 16; i += 256) {
        int n = i >> 4, k8 = (i & 15) << 3;
        uint4 av = *(uint4*)&A_s[n * HKP + k8];
        uint4 rv = *(uint4*)&r_s[n * HKP + k8];
        __half2* ah = (__half2*)&av;
        __half2* rh = (__half2*)&rv;
#pragma unroll
        for (int j = 0; j < 4; j++) ah[j] = __hmul2(ah[j], rh[j]);
        *(uint4*)&A_s[n * HKP + k8] = av;
    }
    __syncthreads();
    for (int i = tid; i < 128 * 16; i += 256) {
        int n = i >> 4, k8 = (i & 15) << 3;
        *(uint4*)&B_s[n * HKP + k8] = *(const uint4*)&g_Wct[n * 128 + k8];
    }
    __syncthreads();

    // ---- P6: GEMM3 candidate + GRU update -> g_h
#pragma unroll
    for (int ch = 0; ch < 2; ch++) {
        float acc[8][4];
#pragma unroll
        for (int i = 0; i < 8; i++)
#pragma unroll
            for (int j = 0; j < 4; j++) acc[i][j] = 0.f;
#pragma unroll
        for (int kt = 0; kt < 8; kt++) {
            uint32_t Af[4]; ldsm_x4(Af, aB + kt * 32);
#pragma unroll
            for (int p = 0; p < 4; p++) {
                uint32_t bf[4];
                ldsm_x4(bf, bB + (uint32_t)(ch * 64 * HKP * 2) + kt * 32 + (uint32_t)(p * 16 * HKP * 2));
                mma_f16(acc[2 * p],     Af, bf);
                mma_f16(acc[2 * p + 1], Af, bf + 2);
            }
        }
#pragma unroll
        for (int nt = 0; nt < 8; nt++) {
            int c = ch * 64 + nt * 8 + q;
#pragma unroll
            for (int hh = 0; hh < 2; hh++) {
                const float* fv = hh ? fB : fA;
                int lrow = hh ? lr1 : lr0;
                int grow = row0 + lrow;
                float v0 = acc[nt][hh * 2]     + g_biasc[c]
                         + fv[0] * g_M6c[c]         + fv[1] * g_M6c[128 + c]
                         + fv[2] * g_M6c[256 + c]   + fv[3] * g_M6c[384 + c]
                         + fv[4] * g_M6c[512 + c]   + fv[5] * g_M6c[640 + c];
                float v1 = acc[nt][hh * 2 + 1] + g_biasc[c + 1]
                         + fv[0] * g_M6c[c + 1]     + fv[1] * g_M6c[129 + c]
                         + fv[2] * g_M6c[257 + c]   + fv[3] * g_M6c[385 + c]
                         + fv[4] * g_M6c[513 + c]   + fv[5] * g_M6c[641 + c];
                float z0 = z_s[lrow * ZKP + c], z1 = z_s[lrow * ZKP + c + 1];
                float2 hp = *(float2*)&g_h[(size_t)grow * 128 + c];
                float2 o;
                o.x = z0 * hp.x + (1.f - z0) * tanhf(v0);
                o.y = z1 * hp.y + (1.f - z1) * tanhf(v1);
                *(float2*)&g_h[(size_t)grow * 128 + c] = o;
            }
        }
    }
}

// ---------------- output head ----------------
__global__ void out_kernel(const float* __restrict__ Wo, const float* __restrict__ bo,
                           float* __restrict__ out) {
    int idx = blockIdx.x * blockDim.x + threadIdx.x;
    if (idx >= NTOT * HORZ) return;
    int i = idx / HORZ, hor = idx - i * HORZ;
    const float* hr = g_h + (size_t)i * HD;
    float s = bo[hor];
#pragma unroll 8
    for (int k = 0; k < HD; k++) s = fmaf(hr[k], Wo[k * HORZ + hor], s);
    int b = i / NNODE, n = i - b * NNODE;
    out[(size_t)(b * HORZ + hor) * NNODE + n] = s;
}

// ---------------- launch ----------------
extern "C" void kernel_launch(void* const* d_in, const int* in_sizes, int n_in,
                              void* d_out, int out_size) {
    const float* x  = (const float*)d_in[0];
    const void*  ei = d_in[1];
    const float* W1 = (const float*)d_in[2];
    const float* b1 = (const float*)d_in[3];
    const float* W2 = (const float*)d_in[4];
    const float* b2 = (const float*)d_in[5];
    const float* Wz = (const float*)d_in[6];
    const float* bz = (const float*)d_in[7];
    const float* Wr = (const float*)d_in[8];
    const float* br = (const float*)d_in[9];
    const float* Wc = (const float*)d_in[10];
    const float* bc = (const float*)d_in[11];
    const float* Wo = (const float*)d_in[12];
    const float* bo = (const float*)d_in[13];
    float* out = (float*)d_out;
    (void)in_sizes; (void)n_in; (void)out_size;

    const int SMEM = 204800;
    cudaFuncSetAttribute(cell_kernel, cudaFuncAttributeMaxDynamicSharedMemorySize, SMEM);

    zero_h_kernel<<<(NTOT * HD + 1023) / 1024, 1024>>>();
    zero_counts_kernel<<<(2 * NNODE + 255) / 256, 256>>>();
    detect_dtype_kernel<<<(2 * NEDGE + 255) / 256, 256>>>(ei);
    set_is64_kernel<<<1, 1>>>();
    count_edges_kernel<<<(NEDGE + 255) / 256, 256>>>(ei);
    norm_kernel<<<(NEDGE + 255) / 256, 256>>>(ei);
    scan_kernel<<<1, 1024>>>();
    fill_kernel<<<(NEDGE + 255) / 256, 256>>>(ei);
    build_bhalf_kernel<<<(98304 + 255) / 256, 256>>>(W2, Wz, Wr, Wc);
    build_zr_fold_kernel<<<(7 * 256 + 255) / 256, 256>>>(W1, b1, Wz, bz, Wr, br);
    build_c_fold_kernel<<<(7 * HD + 255) / 256, 256>>>(W1, b1, Wc, bc);

    for (int t = 0; t < TSTEPS; t++) {
        const float* xt0 = x + (size_t)t * NNODE * INF;   // batch 0, timestep t
        prop2_kernel<<<(NNODE * INF + 127) / 128, 128>>>(xt0, 0);
        prop2_kernel<<<(NNODE * INF + 127) / 128, 128>>>(xt0, 1);
        prop128_kernel<<<NNODE, HD>>>(0);
        prop128_kernel<<<NNODE, HD>>>(1);
        cell_kernel<<<NTOT / 128, 256, SMEM>>>(x, t, b2);
    }

    out_kernel<<<(NTOT * HORZ + 255) / 256, 256>>>(Wo, bo, out);
}

// round 11
// speedup vs baseline: 4.1186x; 1.3227x over previous
#include <cuda_runtime.h>
#include <cuda_fp16.h>
#include <math.h>
#include <cstdint>

#define NTOT   160000
#define NNODE  5000
#define NEDGE  80000
#define TSTEPS 12
#define HD     128
#define HORZ   12
#define INF    2

#define HKP 136   // half stride for K=128 tiles

// ---------------- static device scratch ----------------
__device__ float g_h   [NTOT * HD];
__device__ float g_P1  [NNODE * HD];
__device__ float g_P2  [NNODE * HD];
__device__ float g_X1  [NNODE * INF];
__device__ float g_X2  [NNODE * INF];
__device__ float g_norm[NEDGE];
__device__ int   g_degsrc[NNODE];
__device__ int   g_cnt [NNODE];
__device__ int   g_off [NNODE + 1];
__device__ int   g_cur [NNODE];
__device__ int   g_csrsrc[NEDGE];
__device__ float g_csrw  [NEDGE];
__device__ float g_M6zr  [6 * 2 * HD];
__device__ float g_biaszr[2 * HD];
__device__ float g_M6c   [6 * HD];
__device__ float g_biasc [HD];
__device__ int   g_bad64;
__device__ int   g_is64;

// fp16 transposed weights [n][k] (all K=128)
__device__ __align__(16) __half g_A2t  [128 * 128];  // W2[0]-W2[2]
__device__ __align__(16) __half g_W2bt1[128 * 128];  // W2[1]^T
__device__ __align__(16) __half g_W2bt2[128 * 128];  // 2*W2[2]^T
__device__ __align__(16) __half g_Wzrt [256 * 128];  // bottom [Wz|Wr]
__device__ __align__(16) __half g_Wct  [128 * 128];  // bottom Wc

// ---------------- warp-MMA primitives ----------------
__device__ __forceinline__ uint32_t smem_u32(const void* p) {
    uint32_t a;
    asm("{ .reg .u64 t; cvta.to.shared.u64 t, %1; cvt.u32.u64 %0, t; }" : "=r"(a) : "l"(p));
    return a;
}
__device__ __forceinline__ void ldsm_x4(uint32_t* r, uint32_t addr) {
    asm volatile("ldmatrix.sync.aligned.m8n8.x4.shared.b16 {%0,%1,%2,%3}, [%4];"
        : "=r"(r[0]), "=r"(r[1]), "=r"(r[2]), "=r"(r[3]) : "r"(addr));
}
__device__ __forceinline__ void mma_f16(float* c, const uint32_t* a, const uint32_t* b) {
    asm volatile("mma.sync.aligned.m16n8k16.row.col.f32.f16.f16.f32 "
        "{%0,%1,%2,%3}, {%4,%5,%6,%7}, {%8,%9}, {%0,%1,%2,%3};"
        : "+f"(c[0]), "+f"(c[1]), "+f"(c[2]), "+f"(c[3])
        : "r"(a[0]), "r"(a[1]), "r"(a[2]), "r"(a[3]), "r"(b[0]), "r"(b[1]));
}
__device__ __forceinline__ uint4 cvt8h(const float* a) {
    uint32_t u[4];
#pragma unroll
    for (int i = 0; i < 4; i++) {
        __half h0 = __float2half_rn(a[2 * i]);
        __half h1 = __float2half_rn(a[2 * i + 1]);
        u[i] = (uint32_t)__half_as_ushort(h0) | ((uint32_t)__half_as_ushort(h1) << 16);
    }
    return make_uint4(u[0], u[1], u[2], u[3]);
}
// K=128 GEMM: 128x128 output, acc[ch][nt][4]
__device__ __forceinline__ void do_gemm128(float acc[2][8][4], uint32_t aB, uint32_t bB) {
#pragma unroll
    for (int kt = 0; kt < 8; kt++) {
        uint32_t Af[4]; ldsm_x4(Af, aB + kt * 32);
#pragma unroll
        for (int ch = 0; ch < 2; ch++)
#pragma unroll
            for (int p = 0; p < 4; p++) {
                uint32_t bf[4];
                ldsm_x4(bf, bB + (uint32_t)(ch * 64 * HKP * 2) + kt * 32 + (uint32_t)(p * 16 * HKP * 2));
                mma_f16(acc[ch][2 * p],     Af, bf);
                mma_f16(acc[ch][2 * p + 1], Af, bf + 2);
            }
    }
}

// ---------------- edge dtype probe ----------------
__global__ void detect_dtype_kernel(const void* __restrict__ ei) {
    int e = blockIdx.x * blockDim.x + threadIdx.x;
    if (e >= 2 * NEDGE) return;
    long long v = ((const long long*)ei)[e];
    if (v < 0 || v >= NNODE) atomicOr(&g_bad64, 1);
}
__global__ void set_is64_kernel() { g_is64 = g_bad64 ? 0 : 1; }

__device__ __forceinline__ int edge_at(const void* __restrict__ ei, int idx) {
    int s;
    if (g_is64) s = (int)((const long long*)ei)[idx];
    else        s = ((const int*)ei)[idx];
    if (s < 0) s = 0;
    if (s >= NNODE) s = NNODE - 1;
    return s;
}

// ---------------- setup kernels ----------------
__global__ void zero_h_kernel() {
    int i = blockIdx.x * blockDim.x + threadIdx.x;
    if (i < NTOT * HD) g_h[i] = 0.f;
}
__global__ void zero_counts_kernel() {
    int i = blockIdx.x * blockDim.x + threadIdx.x;
    if (i < NNODE) g_degsrc[i] = 0;
    else if (i < 2 * NNODE) g_cnt[i - NNODE] = 0;
    if (i == 0) g_bad64 = 0;
}
__global__ void count_edges_kernel(const void* __restrict__ ei) {
    int e = blockIdx.x * blockDim.x + threadIdx.x;
    if (e >= NEDGE) return;
    atomicAdd(&g_degsrc[edge_at(ei, e)], 1);
    atomicAdd(&g_cnt[edge_at(ei, NEDGE + e)], 1);
}
__global__ void norm_kernel(const void* __restrict__ ei) {
    int e = blockIdx.x * blockDim.x + threadIdx.x;
    if (e >= NEDGE) return;
    int s = edge_at(ei, e), d = edge_at(ei, NEDGE + e);
    int ds = g_degsrc[s], dd = g_degsrc[d];
    float is = (ds > 0) ? rsqrtf((float)ds) : 0.f;
    float id = (dd > 0) ? rsqrtf((float)dd) : 0.f;
    g_norm[e] = -is * id;
}
__global__ void scan_kernel() {
    __shared__ int sh[1024];
    int t = threadIdx.x;
    int start = t * 5, end = start + 5;
    if (end > NNODE) end = NNODE;
    int s = 0;
    for (int i = start; i < end && i < NNODE; i++) s += g_cnt[i];
    sh[t] = s;
    __syncthreads();
    for (int off = 1; off < 1024; off <<= 1) {
        int v = (t >= off) ? sh[t - off] : 0;
        __syncthreads();
        sh[t] += v;
        __syncthreads();
    }
    int run = (t == 0) ? 0 : sh[t - 1];
    for (int i = start; i < end && i < NNODE; i++) {
        g_off[i] = run; g_cur[i] = run; run += g_cnt[i];
    }
    if (t == 1023) g_off[NNODE] = sh[1023];
}
__global__ void fill_kernel(const void* __restrict__ ei) {
    int e = blockIdx.x * blockDim.x + threadIdx.x;
    if (e >= NEDGE) return;
    int s = edge_at(ei, e), d = edge_at(ei, NEDGE + e);
    int p = atomicAdd(&g_cur[d], 1);
    if (p >= NEDGE) p = NEDGE - 1;
    g_csrsrc[p] = s;
    g_csrw[p]   = g_norm[e];
}

__global__ void build_bhalf_kernel(const float* __restrict__ W2, const float* __restrict__ Wz,
                                   const float* __restrict__ Wr, const float* __restrict__ Wc) {
    int i = blockIdx.x * blockDim.x + threadIdx.x;
    if (i < 16384) {
        int n = i >> 7, k = i & 127;
        g_A2t[n * 128 + k] = __float2half_rn(W2[k * 128 + n] - W2[2 * 16384 + k * 128 + n]);
    } else if (i < 32768) {
        int j = i - 16384; int n = j >> 7, k = j & 127;
        g_W2bt1[n * 128 + k] = __float2half_rn(W2[16384 + k * 128 + n]);
    } else if (i < 49152) {
        int j = i - 32768; int n = j >> 7, k = j & 127;
        g_W2bt2[n * 128 + k] = __float2half_rn(2.f * W2[32768 + k * 128 + n]);
    } else if (i < 81920) {
        int j = i - 49152; int n = j >> 7, k = j & 127;
        float v = (n < 128) ? Wz[(128 + k) * 128 + n] : Wr[(128 + k) * 128 + (n - 128)];
        g_Wzrt[n * 128 + k] = __float2half_rn(v);
    } else if (i < 98304) {
        int j = i - 81920; int n = j >> 7, k = j & 127;
        g_Wct[n * 128 + k] = __float2half_rn(Wc[(128 + k) * 128 + n]);
    }
}

__device__ __forceinline__ float ic_row_elem(const float* W1, const float* b1, int r, int k) {
    switch (r) {
        case 0: return W1[k]        - W1[512 + k];
        case 1: return W1[128 + k]  - W1[640 + k];
        case 2: return W1[256 + k];
        case 3: return W1[384 + k];
        case 4: return 2.f * W1[512 + k];
        case 5: return 2.f * W1[640 + k];
        default: return b1[k];
    }
}
__global__ void build_zr_fold_kernel(const float* __restrict__ W1, const float* __restrict__ b1,
                                     const float* __restrict__ Wz, const float* __restrict__ bz,
                                     const float* __restrict__ Wr, const float* __restrict__ br) {
    int idx = blockIdx.x * blockDim.x + threadIdx.x;
    if (idx >= 7 * 256) return;
    int r = idx / 256, j = idx % 256;
    const float* Wtop = (j < HD) ? Wz : Wr;
    int jj = j & (HD - 1);
    float s = 0.f;
    for (int k = 0; k < HD; k++) s += ic_row_elem(W1, b1, r, k) * Wtop[k * HD + jj];
    if (r < 6) g_M6zr[r * 256 + j] = s;
    else       g_biaszr[j] = s + ((j < HD) ? bz[jj] : br[jj]);
}
__global__ void build_c_fold_kernel(const float* __restrict__ W1, const float* __restrict__ b1,
                                    const float* __restrict__ Wc, const float* __restrict__ bc) {
    int idx = blockIdx.x * blockDim.x + threadIdx.x;
    if (idx >= 7 * HD) return;
    int r = idx / HD, j = idx % HD;
    float s = 0.f;
    for (int k = 0; k < HD; k++) s += ic_row_elem(W1, b1, r, k) * Wc[k * HD + j];
    if (r < 6) g_M6c[r * HD + j] = s;
    else       g_biasc[j] = s + bc[j];
}

// ---------------- graph propagation ----------------
__global__ void prop128_kernel(int sel) {
    const float* tin  = sel ? g_P1 : g_h;
    float*       tout = sel ? g_P2 : g_P1;
    int d = blockIdx.x, j = threadIdx.x;
    int p0 = g_off[d], p1 = g_off[d + 1];
    float acc = 0.f;
    for (int p = p0; p < p1; p++)
        acc = fmaf(g_csrw[p], tin[g_csrsrc[p] * HD + j], acc);
    tout[d * HD + j] = acc;
}
__global__ void prop2_kernel(const float* __restrict__ xin, int sel) {
    int idx = blockIdx.x * blockDim.x + threadIdx.x;
    if (idx >= NNODE * INF) return;
    int d = idx >> 1, c = idx & 1;
    const float* tin  = sel ? g_X1 : xin;
    float*       tout = sel ? g_X2 : g_X1;
    int p0 = g_off[d], p1 = g_off[d + 1];
    float acc = 0.f;
    for (int p = p0; p < p1; p++)
        acc = fmaf(g_csrw[p], tin[g_csrsrc[p] * INF + c], acc);
    tout[idx] = acc;
}

// ---------------- fused TGCN cell (2 CTA/SM) ----------------
// smem: A_s [128][HKP] half (34816 B) | B_s [128][HKP] half (34816 B) = 69632 B
__global__ __launch_bounds__(256, 2)
void cell_kernel(const float* __restrict__ x, int t, const float* __restrict__ b2) {
    extern __shared__ __align__(16) char sm[];
    __half* A_s = (__half*)sm;
    __half* B_s = (__half*)(sm + 34816);

    int tid = threadIdx.x, lane = tid & 31, w = tid >> 5;
    int row0 = blockIdx.x * 128;
    bool corr = (row0 < NNODE);
    int g = lane >> 2, q = (lane & 3) << 1;
    int lr0 = w * 16 + g, lr1 = lr0 + 8;

    // staging coords
    int srr = tid >> 1, skb = (tid & 1) << 6;

    // stage a K=128 fp32 source tile -> A_s fp16 (guard rows >= limit to 0)
    auto stageA = [&](const float* base, int limit) {
        int gr = row0 + srr;
#pragma unroll
        for (int kk = 0; kk < 64; kk += 8) {
            int k0 = skb + kk;
            float a[8];
            if (gr < limit) {
                const float* src = base + (size_t)gr * 128 + k0;
                float4 v0 = *(const float4*)(src);
                float4 v1 = *(const float4*)(src + 4);
                a[0]=v0.x; a[1]=v0.y; a[2]=v0.z; a[3]=v0.w; a[4]=v1.x; a[5]=v1.y; a[6]=v1.z; a[7]=v1.w;
            } else {
#pragma unroll
                for (int i = 0; i < 8; i++) a[i] = 0.f;
            }
            *(uint4*)&A_s[srr * HKP + k0] = cvt8h(a);
        }
    };
    auto stageB = [&](const __half* Bw) {
        for (int i = tid; i < 128 * 16; i += 256) {
            int n = i >> 4, k8 = (i & 15) << 3;
            *(uint4*)&B_s[n * HKP + k8] = *(const uint4*)&Bw[n * 128 + k8];
        }
    };

    uint32_t aB = smem_u32(A_s) + ((uint32_t)((lr0 - g + (lane & 15)) * HKP + ((lane >> 4) << 3)) << 1);
    uint32_t bB = smem_u32(B_s) + ((uint32_t)(((lane & 7) + ((lane & 16) >> 1)) * HKP) << 1) + ((lane & 8) << 1);

    // rank-6 features for this thread's two rows
    float fA[6], fB[6];
#pragma unroll
    for (int hh = 0; hh < 2; hh++) {
        int row = row0 + (hh ? lr1 : lr0);
        float* f = hh ? fB : fA;
        int b = row / NNODE, n = row - b * NNODE;
        const float* xr = x + ((size_t)(b * TSTEPS + t) * NNODE + n) * 2;
        f[0] = xr[0]; f[1] = xr[1];
        if (row < NNODE) {
            f[2] = g_X1[row * 2]; f[3] = g_X1[row * 2 + 1];
            f[4] = g_X2[row * 2]; f[5] = g_X2[row * 2 + 1];
        } else { f[2] = 0.f; f[3] = 0.f; f[4] = 0.f; f[5] = 0.f; }
    }

    // ---- GEMM1: hc = h @ A2t^T (+ correction GEMMs for rows < NNODE)
    float hca[2][8][4];
#pragma unroll
    for (int c = 0; c < 2; c++)
#pragma unroll
        for (int i = 0; i < 8; i++)
#pragma unroll
            for (int j = 0; j < 4; j++) hca[c][i][j] = 0.f;

    stageA(g_h, NTOT);
    stageB(g_A2t);
    __syncthreads();
    do_gemm128(hca, aB, bB);

    if (corr) {
        __syncthreads();
        stageA(g_P1, NNODE);
        stageB(g_W2bt1);
        __syncthreads();
        do_gemm128(hca, aB, bB);
        __syncthreads();
        stageA(g_P2, NNODE);
        stageB(g_W2bt2);
        __syncthreads();
        do_gemm128(hca, aB, bB);
    }

    // ---- write hc + b2 -> A_s (fp16); stage Bz
    __syncthreads();
#pragma unroll
    for (int ch = 0; ch < 2; ch++)
#pragma unroll
        for (int nt = 0; nt < 8; nt++) {
            int c = ch * 64 + nt * 8 + q;
            float b0 = b2[c], b1 = b2[c + 1];
            *(__half2*)&A_s[lr0 * HKP + c] = __floats2half2_rn(hca[ch][nt][0] + b0, hca[ch][nt][1] + b1);
            *(__half2*)&A_s[lr1 * HKP + c] = __floats2half2_rn(hca[ch][nt][2] + b0, hca[ch][nt][3] + b1);
        }
    stageB(g_Wzrt);          // z half of [Wz|Wr]
    __syncthreads();

    // ---- GEMM-z: z kept packed fp16 in regs
    uint32_t zp[2][8][2];
    {
        float acc[2][8][4];
#pragma unroll
        for (int c = 0; c < 2; c++)
#pragma unroll
            for (int i = 0; i < 8; i++)
#pragma unroll
                for (int j = 0; j < 4; j++) acc[c][i][j] = 0.f;
        do_gemm128(acc, aB, bB);
#pragma unroll
        for (int ch = 0; ch < 2; ch++)
#pragma unroll
            for (int nt = 0; nt < 8; nt++) {
                int gc = ch * 64 + nt * 8 + q;
#pragma unroll
                for (int hh = 0; hh < 2; hh++) {
                    const float* fv = hh ? fB : fA;
                    float v0 = acc[ch][nt][hh * 2]     + g_biaszr[gc]
                             + fv[0] * g_M6zr[gc]        + fv[1] * g_M6zr[256 + gc]
                             + fv[2] * g_M6zr[512 + gc]  + fv[3] * g_M6zr[768 + gc]
                             + fv[4] * g_M6zr[1024 + gc] + fv[5] * g_M6zr[1280 + gc];
                    float v1 = acc[ch][nt][hh * 2 + 1] + g_biaszr[gc + 1]
                             + fv[0] * g_M6zr[gc + 1]      + fv[1] * g_M6zr[257 + gc]
                             + fv[2] * g_M6zr[513 + gc]    + fv[3] * g_M6zr[769 + gc]
                             + fv[4] * g_M6zr[1025 + gc]   + fv[5] * g_M6zr[1281 + gc];
                    __half2 zh = __floats2half2_rn(1.f / (1.f + expf(-v0)), 1.f / (1.f + expf(-v1)));
                    zp[ch][nt][hh] = *(uint32_t*)&zh;
                }
            }
    }
    __syncthreads();
    stageB(g_Wzrt + 128 * 128);   // r half
    __syncthreads();

    // ---- GEMM-r: sigmoid, then multiply into A_s (hc) in place
    {
        float acc[2][8][4];
#pragma unroll
        for (int c = 0; c < 2; c++)
#pragma unroll
            for (int i = 0; i < 8; i++)
#pragma unroll
                for (int j = 0; j < 4; j++) acc[c][i][j] = 0.f;
        do_gemm128(acc, aB, bB);
        // sigmoid in place
#pragma unroll
        for (int ch = 0; ch < 2; ch++)
#pragma unroll
            for (int nt = 0; nt < 8; nt++) {
                int gc = 128 + ch * 64 + nt * 8 + q;
#pragma unroll
                for (int hh = 0; hh < 2; hh++) {
                    const float* fv = hh ? fB : fA;
                    float v0 = acc[ch][nt][hh * 2]     + g_biaszr[gc]
                             + fv[0] * g_M6zr[gc]        + fv[1] * g_M6zr[256 + gc]
                             + fv[2] * g_M6zr[512 + gc]  + fv[3] * g_M6zr[768 + gc]
                             + fv[4] * g_M6zr[1024 + gc] + fv[5] * g_M6zr[1280 + gc];
                    float v1 = acc[ch][nt][hh * 2 + 1] + g_biaszr[gc + 1]
                             + fv[0] * g_M6zr[gc + 1]      + fv[1] * g_M6zr[257 + gc]
                             + fv[2] * g_M6zr[513 + gc]    + fv[3] * g_M6zr[769 + gc]
                             + fv[4] * g_M6zr[1025 + gc]   + fv[5] * g_M6zr[1281 + gc];
                    acc[ch][nt][hh * 2]     = 1.f / (1.f + expf(-v0));
                    acc[ch][nt][hh * 2 + 1] = 1.f / (1.f + expf(-v1));
                }
            }
        __syncthreads();   // all warps done reading A_s (hc) via ldsm
#pragma unroll
        for (int ch = 0; ch < 2; ch++)
#pragma unroll
            for (int nt = 0; nt < 8; nt++) {
                int c = ch * 64 + nt * 8 + q;
#pragma unroll
                for (int hh = 0; hh < 2; hh++) {
                    int lrow = hh ? lr1 : lr0;
                    __half2* hp = (__half2*)&A_s[lrow * HKP + c];
                    __half2 rv = __floats2half2_rn(acc[ch][nt][hh * 2], acc[ch][nt][hh * 2 + 1]);
                    *hp = __hmul2(*hp, rv);
                }
            }
    }
    stageB(g_Wct);
    __syncthreads();

    // ---- GEMM3: candidate + GRU update -> g_h
    {
        float acc[2][8][4];
#pragma unroll
        for (int c = 0; c < 2; c++)
#pragma unroll
            for (int i = 0; i < 8; i++)
#pragma unroll
                for (int j = 0; j < 4; j++) acc[c][i][j] = 0.f;
        do_gemm128(acc, aB, bB);
#pragma unroll
        for (int ch = 0; ch < 2; ch++)
#pragma unroll
            for (int nt = 0; nt < 8; nt++) {
                int c = ch * 64 + nt * 8 + q;
#pragma unroll
                for (int hh = 0; hh < 2; hh++) {
                    const float* fv = hh ? fB : fA;
                    int grow = row0 + (hh ? lr1 : lr0);
                    float v0 = acc[ch][nt][hh * 2]     + g_biasc[c]
                             + fv[0] * g_M6c[c]         + fv[1] * g_M6c[128 + c]
                             + fv[2] * g_M6c[256 + c]   + fv[3] * g_M6c[384 + c]
                             + fv[4] * g_M6c[512 + c]   + fv[5] * g_M6c[640 + c];
                    float v1 = acc[ch][nt][hh * 2 + 1] + g_biasc[c + 1]
                             + fv[0] * g_M6c[c + 1]     + fv[1] * g_M6c[129 + c]
                             + fv[2] * g_M6c[257 + c]   + fv[3] * g_M6c[385 + c]
                             + fv[4] * g_M6c[513 + c]   + fv[5] * g_M6c[641 + c];
                    float2 zv = __half22float2(*(__half2*)&zp[ch][nt][hh]);
                    float2 hp = *(float2*)&g_h[(size_t)grow * 128 + c];
                    float2 o;
                    o.x = zv.x * hp.x + (1.f - zv.x) * tanhf(v0);
                    o.y = zv.y * hp.y + (1.f - zv.y) * tanhf(v1);
                    *(float2*)&g_h[(size_t)grow * 128 + c] = o;
                }
            }
    }
}

// ---------------- output head ----------------
__global__ void out_kernel(const float* __restrict__ Wo, const float* __restrict__ bo,
                           float* __restrict__ out) {
    int idx = blockIdx.x * blockDim.x + threadIdx.x;
    if (idx >= NTOT * HORZ) return;
    int i = idx / HORZ, hor = idx - i * HORZ;
    const float* hr = g_h + (size_t)i * HD;
    float s = bo[hor];
#pragma unroll 8
    for (int k = 0; k < HD; k++) s = fmaf(hr[k], Wo[k * HORZ + hor], s);
    int b = i / NNODE, n = i - b * NNODE;
    out[(size_t)(b * HORZ + hor) * NNODE + n] = s;
}

// ---------------- launch ----------------
extern "C" void kernel_launch(void* const* d_in, const int* in_sizes, int n_in,
                              void* d_out, int out_size) {
    const float* x  = (const float*)d_in[0];
    const void*  ei = d_in[1];
    const float* W1 = (const float*)d_in[2];
    const float* b1 = (const float*)d_in[3];
    const float* W2 = (const float*)d_in[4];
    const float* b2 = (const float*)d_in[5];
    const float* Wz = (const float*)d_in[6];
    const float* bz = (const float*)d_in[7];
    const float* Wr = (const float*)d_in[8];
    const float* br = (const float*)d_in[9];
    const float* Wc = (const float*)d_in[10];
    const float* bc = (const float*)d_in[11];
    const float* Wo = (const float*)d_in[12];
    const float* bo = (const float*)d_in[13];
    float* out = (float*)d_out;
    (void)in_sizes; (void)n_in; (void)out_size;

    const int SMEM = 69632;
    cudaFuncSetAttribute(cell_kernel, cudaFuncAttributeMaxDynamicSharedMemorySize, SMEM);

    zero_h_kernel<<<(NTOT * HD + 1023) / 1024, 1024>>>();
    zero_counts_kernel<<<(2 * NNODE + 255) / 256, 256>>>();
    detect_dtype_kernel<<<(2 * NEDGE + 255) / 256, 256>>>(ei);
    set_is64_kernel<<<1, 1>>>();
    count_edges_kernel<<<(NEDGE + 255) / 256, 256>>>(ei);
    norm_kernel<<<(NEDGE + 255) / 256, 256>>>(ei);
    scan_kernel<<<1, 1024>>>();
    fill_kernel<<<(NEDGE + 255) / 256, 256>>>(ei);
    build_bhalf_kernel<<<(98304 + 255) / 256, 256>>>(W2, Wz, Wr, Wc);
    build_zr_fold_kernel<<<(7 * 256 + 255) / 256, 256>>>(W1, b1, Wz, bz, Wr, br);
    build_c_fold_kernel<<<(7 * HD + 255) / 256, 256>>>(W1, b1, Wc, bc);

    for (int t = 0; t < TSTEPS; t++) {
        const float* xt0 = x + (size_t)t * NNODE * INF;   // batch 0, timestep t
        prop2_kernel<<<(NNODE * INF + 127) / 128, 128>>>(xt0, 0);
        prop2_kernel<<<(NNODE * INF + 127) / 128, 128>>>(xt0, 1);
        prop128_kernel<<<NNODE, HD>>>(0);
        prop128_kernel<<<NNODE, HD>>>(1);
        cell_kernel<<<NTOT / 128, 256, SMEM>>>(x, t, b2);
    }

    out_kernel<<<(NTOT * HORZ + 255) / 256, 256>>>(Wo, bo, out);
}

// round 12
// speedup vs baseline: 4.7499x; 1.1533x over previous
#include <cuda_runtime.h>
#include <cuda_fp16.h>
#include <math.h>
#include <cstdint>

#define NTOT   160000
#define NNODE  5000
#define NEDGE  80000
#define TSTEPS 12
#define HD     128
#define HORZ   12
#define INF    2

#define EKP 152   // half stride for extended K=144 tiles

// ---------------- static device scratch ----------------
__device__ float g_h   [NTOT * HD];
__device__ float g_P1  [NNODE * HD];
__device__ float g_P2  [NNODE * HD];
__device__ float g_X1  [NNODE * INF];
__device__ float g_X2  [NNODE * INF];
__device__ float g_norm[NEDGE];
__device__ int   g_degsrc[NNODE];
__device__ int   g_cnt [NNODE];
__device__ int   g_off [NNODE + 1];
__device__ int   g_cur [NNODE];
__device__ int   g_csrsrc[NEDGE];
__device__ float g_csrw  [NEDGE];
__device__ float g_M6zr  [6 * 2 * HD];
__device__ float g_biaszr[2 * HD];
__device__ float g_M6c   [6 * HD];
__device__ float g_biasc [HD];
__device__ int   g_bad64;
__device__ int   g_is64;

// extended fp16 B tiles [n][144]: 0:A2eff 1:W2[1] 2:2*W2[2] 3:Wz+M6z+bias 4:Wr+M6r+bias 5:Wc+M6c+bias
__device__ __align__(16) __half g_Bext[6][128 * 144];

// ---------------- warp-MMA primitives ----------------
__device__ __forceinline__ uint32_t smem_u32(const void* p) {
    uint32_t a;
    asm("{ .reg .u64 t; cvta.to.shared.u64 t, %1; cvt.u32.u64 %0, t; }" : "=r"(a) : "l"(p));
    return a;
}
__device__ __forceinline__ void ldsm_x4(uint32_t* r, uint32_t addr) {
    asm volatile("ldmatrix.sync.aligned.m8n8.x4.shared.b16 {%0,%1,%2,%3}, [%4];"
        : "=r"(r[0]), "=r"(r[1]), "=r"(r[2]), "=r"(r[3]) : "r"(addr));
}
__device__ __forceinline__ void mma_f16(float* c, const uint32_t* a, const uint32_t* b) {
    asm volatile("mma.sync.aligned.m16n8k16.row.col.f32.f16.f16.f32 "
        "{%0,%1,%2,%3}, {%4,%5,%6,%7}, {%8,%9}, {%0,%1,%2,%3};"
        : "+f"(c[0]), "+f"(c[1]), "+f"(c[2]), "+f"(c[3])
        : "r"(a[0]), "r"(a[1]), "r"(a[2]), "r"(a[3]), "r"(b[0]), "r"(b[1]));
}
__device__ __forceinline__ uint4 cvt8h(const float* a) {
    uint32_t u[4];
#pragma unroll
    for (int i = 0; i < 4; i++) {
        __half h0 = __float2half_rn(a[2 * i]);
        __half h1 = __float2half_rn(a[2 * i + 1]);
        u[i] = (uint32_t)__half_as_ushort(h0) | ((uint32_t)__half_as_ushort(h1) << 16);
    }
    return make_uint4(u[0], u[1], u[2], u[3]);
}
__device__ __forceinline__ float fsig(float v)  { return 1.f / (1.f + __expf(-v)); }
__device__ __forceinline__ float ftanh(float v) { return 1.f - 2.f / (__expf(2.f * v) + 1.f); }

template <int NK>
__device__ __forceinline__ void do_gemm(float acc[2][8][4], uint32_t aB, uint32_t bB) {
#pragma unroll
    for (int kt = 0; kt < NK; kt++) {
        uint32_t Af[4]; ldsm_x4(Af, aB + kt * 32);
#pragma unroll
        for (int ch = 0; ch < 2; ch++)
#pragma unroll
            for (int p = 0; p < 4; p++) {
                uint32_t bf[4];
                ldsm_x4(bf, bB + (uint32_t)(ch * 64 * EKP * 2) + kt * 32 + (uint32_t)(p * 16 * EKP * 2));
                mma_f16(acc[ch][2 * p],     Af, bf);
                mma_f16(acc[ch][2 * p + 1], Af, bf + 2);
            }
    }
}

// ---------------- edge dtype probe ----------------
__global__ void detect_dtype_kernel(const void* __restrict__ ei) {
    int e = blockIdx.x * blockDim.x + threadIdx.x;
    if (e >= 2 * NEDGE) return;
    long long v = ((const long long*)ei)[e];
    if (v < 0 || v >= NNODE) atomicOr(&g_bad64, 1);
}
__global__ void set_is64_kernel() { g_is64 = g_bad64 ? 0 : 1; }

__device__ __forceinline__ int edge_at(const void* __restrict__ ei, int idx) {
    int s;
    if (g_is64) s = (int)((const long long*)ei)[idx];
    else        s = ((const int*)ei)[idx];
    if (s < 0) s = 0;
    if (s >= NNODE) s = NNODE - 1;
    return s;
}

// ---------------- setup kernels ----------------
__global__ void zero_h_kernel() {
    int i = blockIdx.x * blockDim.x + threadIdx.x;
    if (i < NTOT * HD) g_h[i] = 0.f;
}
__global__ void zero_counts_kernel() {
    int i = blockIdx.x * blockDim.x + threadIdx.x;
    if (i < NNODE) g_degsrc[i] = 0;
    else if (i < 2 * NNODE) g_cnt[i - NNODE] = 0;
    if (i == 0) g_bad64 = 0;
}
__global__ void count_edges_kernel(const void* __restrict__ ei) {
    int e = blockIdx.x * blockDim.x + threadIdx.x;
    if (e >= NEDGE) return;
    atomicAdd(&g_degsrc[edge_at(ei, e)], 1);
    atomicAdd(&g_cnt[edge_at(ei, NEDGE + e)], 1);
}
__global__ void norm_kernel(const void* __restrict__ ei) {
    int e = blockIdx.x * blockDim.x + threadIdx.x;
    if (e >= NEDGE) return;
    int s = edge_at(ei, e), d = edge_at(ei, NEDGE + e);
    int ds = g_degsrc[s], dd = g_degsrc[d];
    float is = (ds > 0) ? rsqrtf((float)ds) : 0.f;
    float id = (dd > 0) ? rsqrtf((float)dd) : 0.f;
    g_norm[e] = -is * id;
}
__global__ void scan_kernel() {
    __shared__ int sh[1024];
    int t = threadIdx.x;
    int start = t * 5, end = start + 5;
    if (end > NNODE) end = NNODE;
    int s = 0;
    for (int i = start; i < end && i < NNODE; i++) s += g_cnt[i];
    sh[t] = s;
    __syncthreads();
    for (int off = 1; off < 1024; off <<= 1) {
        int v = (t >= off) ? sh[t - off] : 0;
        __syncthreads();
        sh[t] += v;
        __syncthreads();
    }
    int run = (t == 0) ? 0 : sh[t - 1];
    for (int i = start; i < end && i < NNODE; i++) {
        g_off[i] = run; g_cur[i] = run; run += g_cnt[i];
    }
    if (t == 1023) g_off[NNODE] = sh[1023];
}
__global__ void fill_kernel(const void* __restrict__ ei) {
    int e = blockIdx.x * blockDim.x + threadIdx.x;
    if (e >= NEDGE) return;
    int s = edge_at(ei, e), d = edge_at(ei, NEDGE + e);
    int p = atomicAdd(&g_cur[d], 1);
    if (p >= NEDGE) p = NEDGE - 1;
    g_csrsrc[p] = s;
    g_csrw[p]   = g_norm[e];
}

__device__ __forceinline__ float ic_row_elem(const float* W1, const float* b1, int r, int k) {
    switch (r) {
        case 0: return W1[k]        - W1[512 + k];
        case 1: return W1[128 + k]  - W1[640 + k];
        case 2: return W1[256 + k];
        case 3: return W1[384 + k];
        case 4: return 2.f * W1[512 + k];
        case 5: return 2.f * W1[640 + k];
        default: return b1[k];
    }
}
__global__ void build_zr_fold_kernel(const float* __restrict__ W1, const float* __restrict__ b1,
                                     const float* __restrict__ Wz, const float* __restrict__ bz,
                                     const float* __restrict__ Wr, const float* __restrict__ br) {
    int idx = blockIdx.x * blockDim.x + threadIdx.x;
    if (idx >= 7 * 256) return;
    int r = idx / 256, j = idx % 256;
    const float* Wtop = (j < HD) ? Wz : Wr;
    int jj = j & (HD - 1);
    float s = 0.f;
    for (int k = 0; k < HD; k++) s += ic_row_elem(W1, b1, r, k) * Wtop[k * HD + jj];
    if (r < 6) g_M6zr[r * 256 + j] = s;
    else       g_biaszr[j] = s + ((j < HD) ? bz[jj] : br[jj]);
}
__global__ void build_c_fold_kernel(const float* __restrict__ W1, const float* __restrict__ b1,
                                    const float* __restrict__ Wc, const float* __restrict__ bc) {
    int idx = blockIdx.x * blockDim.x + threadIdx.x;
    if (idx >= 7 * HD) return;
    int r = idx / HD, j = idx % HD;
    float s = 0.f;
    for (int k = 0; k < HD; k++) s += ic_row_elem(W1, b1, r, k) * Wc[k * HD + j];
    if (r < 6) g_M6c[r * HD + j] = s;
    else       g_biasc[j] = s + bc[j];
}

// extended B tiles; MUST run after fold kernels
__global__ void build_bext_kernel(const float* __restrict__ W2, const float* __restrict__ Wz,
                                  const float* __restrict__ Wr, const float* __restrict__ Wc,
                                  const float* __restrict__ b2) {
    int idx = blockIdx.x * blockDim.x + threadIdx.x;
    if (idx >= 6 * 128 * 144) return;
    int a = idx / 18432, rem = idx % 18432;
    int n = rem / 144, k = rem % 144;
    float v = 0.f;
    if (a == 0) {
        if (k < 128)       v = W2[k * 128 + n] - W2[32768 + k * 128 + n];
        else if (k == 134) v = b2[n];
    } else if (a == 1) {
        if (k < 128) v = W2[16384 + k * 128 + n];
    } else if (a == 2) {
        if (k < 128) v = 2.f * W2[32768 + k * 128 + n];
    } else if (a == 3) {
        if (k < 128)       v = Wz[(128 + k) * 128 + n];
        else if (k < 134)  v = g_M6zr[(k - 128) * 256 + n];
        else if (k == 134) v = g_biaszr[n];
    } else if (a == 4) {
        if (k < 128)       v = Wr[(128 + k) * 128 + n];
        else if (k < 134)  v = g_M6zr[(k - 128) * 256 + 128 + n];
        else if (k == 134) v = g_biaszr[128 + n];
    } else {
        if (k < 128)       v = Wc[(128 + k) * 128 + n];
        else if (k < 134)  v = g_M6c[(k - 128) * 128 + n];
        else if (k == 134) v = g_biasc[n];
    }
    g_Bext[a][n * 144 + k] = __float2half_rn(v);
}

// ---------------- graph propagation ----------------
__global__ void prop128_kernel(int sel) {
    const float* tin  = sel ? g_P1 : g_h;
    float*       tout = sel ? g_P2 : g_P1;
    int d = blockIdx.x, j = threadIdx.x;
    int p0 = g_off[d], p1 = g_off[d + 1];
    float acc = 0.f;
    for (int p = p0; p < p1; p++)
        acc = fmaf(g_csrw[p], tin[g_csrsrc[p] * HD + j], acc);
    tout[d * HD + j] = acc;
}
__global__ void prop2_kernel(const float* __restrict__ xin, int sel) {
    int idx = blockIdx.x * blockDim.x + threadIdx.x;
    if (idx >= NNODE * INF) return;
    int d = idx >> 1, c = idx & 1;
    const float* tin  = sel ? g_X1 : xin;
    float*       tout = sel ? g_X2 : g_X1;
    int p0 = g_off[d], p1 = g_off[d + 1];
    float acc = 0.f;
    for (int p = p0; p < p1; p++)
        acc = fmaf(g_csrw[p], tin[g_csrsrc[p] * INF + c], acc);
    tout[idx] = acc;
}

// ---------------- fused TGCN cell (2 CTA/SM, rank6+bias folded into GEMM) ----------------
// smem: A_s [128][EKP] half (38912 B) | B_s [128][EKP] half (38912 B) = 77824 B
__global__ __launch_bounds__(256, 2)
void cell_kernel(const float* __restrict__ x, int t) {
    extern __shared__ __align__(16) char sm[];
    __half* A_s = (__half*)sm;
    __half* B_s = (__half*)(sm + 38912);

    int tid = threadIdx.x, lane = tid & 31, w = tid >> 5;
    int row0 = blockIdx.x * 128;
    bool corr = (row0 < NNODE);
    int g = lane >> 2, q = (lane & 3) << 1;
    int lr0 = w * 16 + g, lr1 = lr0 + 8;

    int srr = tid >> 1, skb = (tid & 1) << 6;

    auto stageA = [&](const float* base, int limit) {
        int gr = row0 + srr;
#pragma unroll
        for (int kk = 0; kk < 64; kk += 8) {
            int k0 = skb + kk;
            float a[8];
            if (gr < limit) {
                const float* src = base + (size_t)gr * 128 + k0;
                float4 v0 = *(const float4*)(src);
                float4 v1 = *(const float4*)(src + 4);
                a[0]=v0.x; a[1]=v0.y; a[2]=v0.z; a[3]=v0.w; a[4]=v1.x; a[5]=v1.y; a[6]=v1.z; a[7]=v1.w;
            } else {
#pragma unroll
                for (int i = 0; i < 8; i++) a[i] = 0.f;
            }
            *(uint4*)&A_s[srr * EKP + k0] = cvt8h(a);
        }
    };
    auto stageB = [&](int sel) {
        const __half* Bw = g_Bext[sel];
        for (int i = tid; i < 128 * 18; i += 256) {
            int n = i / 18, k8 = (i % 18) << 3;
            *(uint4*)&B_s[n * EKP + k8] = *(const uint4*)&Bw[n * 144 + k8];
        }
    };

    uint32_t aB = smem_u32(A_s) + ((uint32_t)((lr0 - g + (lane & 15)) * EKP + ((lane >> 4) << 3)) << 1);
    uint32_t bB = smem_u32(B_s) + ((uint32_t)(((lane & 7) + ((lane & 16) >> 1)) * EKP) << 1) + ((lane & 8) << 1);

    // ---- stage h + f-columns; stage B0
    stageA(g_h, NTOT);
    if (tid & 1) {   // one thread per row writes the extension columns (persist across gate GEMMs)
        int row = row0 + srr;
        int b = row / NNODE, n = row - b * NNODE;
        const float* xr = x + ((size_t)(b * TSTEPS + t) * NNODE + n) * 2;
        float fa[8] = {xr[0], xr[1], 0.f, 0.f, 0.f, 0.f, 1.f, 0.f};
        if (row < NNODE) {
            fa[2] = g_X1[row * 2]; fa[3] = g_X1[row * 2 + 1];
            fa[4] = g_X2[row * 2]; fa[5] = g_X2[row * 2 + 1];
        }
        *(uint4*)&A_s[srr * EKP + 128] = cvt8h(fa);
        float fz[8] = {0.f, 0.f, 0.f, 0.f, 0.f, 0.f, 0.f, 0.f};
        *(uint4*)&A_s[srr * EKP + 136] = cvt8h(fz);
    }
    stageB(0);
    __syncthreads();

    // ---- GEMM1: hc = [h|f,1] @ Bext0^T  (b2 folded at k=134)
    float hca[2][8][4];
#pragma unroll
    for (int c = 0; c < 2; c++)
#pragma unroll
        for (int i = 0; i < 8; i++)
#pragma unroll
            for (int j = 0; j < 4; j++) hca[c][i][j] = 0.f;
    do_gemm<9>(hca, aB, bB);

    if (corr) {
        __syncthreads();
        stageA(g_P1, NNODE);
        stageB(1);
        __syncthreads();
        do_gemm<8>(hca, aB, bB);
        __syncthreads();
        stageA(g_P2, NNODE);
        stageB(2);
        __syncthreads();
        do_gemm<8>(hca, aB, bB);
    }

    // ---- write hc -> A_s cols 0..127 (f columns persist); stage Bz
    __syncthreads();
#pragma unroll
    for (int ch = 0; ch < 2; ch++)
#pragma unroll
        for (int nt = 0; nt < 8; nt++) {
            int c = ch * 64 + nt * 8 + q;
            *(__half2*)&A_s[lr0 * EKP + c] = __floats2half2_rn(hca[ch][nt][0], hca[ch][nt][1]);
            *(__half2*)&A_s[lr1 * EKP + c] = __floats2half2_rn(hca[ch][nt][2], hca[ch][nt][3]);
        }
    stageB(3);
    __syncthreads();

    // ---- GEMM-z: sigmoid only (rank6+bias already in), z packed fp16 in regs
    uint32_t zp[2][8][2];
    {
        float acc[2][8][4];
#pragma unroll
        for (int c = 0; c < 2; c++)
#pragma unroll
            for (int i = 0; i < 8; i++)
#pragma unroll
                for (int j = 0; j < 4; j++) acc[c][i][j] = 0.f;
        do_gemm<9>(acc, aB, bB);
#pragma unroll
        for (int ch = 0; ch < 2; ch++)
#pragma unroll
            for (int nt = 0; nt < 8; nt++)
#pragma unroll
                for (int hh = 0; hh < 2; hh++) {
                    __half2 zh = __floats2half2_rn(fsig(acc[ch][nt][hh * 2]), fsig(acc[ch][nt][hh * 2 + 1]));
                    zp[ch][nt][hh] = *(uint32_t*)&zh;
                }
    }
    __syncthreads();
    stageB(4);
    __syncthreads();

    // ---- GEMM-r: sigmoid, multiply into A_s (hc) in place
    {
        float acc[2][8][4];
#pragma unroll
        for (int c = 0; c < 2; c++)
#pragma unroll
            for (int i = 0; i < 8; i++)
#pragma unroll
                for (int j = 0; j < 4; j++) acc[c][i][j] = 0.f;
        do_gemm<9>(acc, aB, bB);
#pragma unroll
        for (int ch = 0; ch < 2; ch++)
#pragma unroll
            for (int nt = 0; nt < 8; nt++)
#pragma unroll
                for (int j = 0; j < 4; j++)
                    acc[ch][nt][j] = fsig(acc[ch][nt][j]);
        __syncthreads();   // all warps done reading A_s via ldsm
#pragma unroll
        for (int ch = 0; ch < 2; ch++)
#pragma unroll
            for (int nt = 0; nt < 8; nt++) {
                int c = ch * 64 + nt * 8 + q;
#pragma unroll
                for (int hh = 0; hh < 2; hh++) {
                    int lrow = hh ? lr1 : lr0;
                    __half2* hp = (__half2*)&A_s[lrow * EKP + c];
                    __half2 rv = __floats2half2_rn(acc[ch][nt][hh * 2], acc[ch][nt][hh * 2 + 1]);
                    *hp = __hmul2(*hp, rv);
                }
            }
    }
    stageB(5);
    __syncthreads();

    // ---- GEMM3: candidate + GRU update -> g_h
    {
        float acc[2][8][4];
#pragma unroll
        for (int c = 0; c < 2; c++)
#pragma unroll
            for (int i = 0; i < 8; i++)
#pragma unroll
                for (int j = 0; j < 4; j++) acc[c][i][j] = 0.f;
        do_gemm<9>(acc, aB, bB);
#pragma unroll
        for (int ch = 0; ch < 2; ch++)
#pragma unroll
            for (int nt = 0; nt < 8; nt++) {
                int c = ch * 64 + nt * 8 + q;
#pragma unroll
                for (int hh = 0; hh < 2; hh++) {
                    int grow = row0 + (hh ? lr1 : lr0);
                    float t0 = ftanh(acc[ch][nt][hh * 2]);
                    float t1 = ftanh(acc[ch][nt][hh * 2 + 1]);
                    float2 zv = __half22float2(*(__half2*)&zp[ch][nt][hh]);
                    float2 hp = *(float2*)&g_h[(size_t)grow * 128 + c];
                    float2 o;
                    o.x = zv.x * hp.x + (1.f - zv.x) * t0;
                    o.y = zv.y * hp.y + (1.f - zv.y) * t1;
                    *(float2*)&g_h[(size_t)grow * 128 + c] = o;
                }
            }
    }
}

// ---------------- output head ----------------
__global__ void out_kernel(const float* __restrict__ Wo, const float* __restrict__ bo,
                           float* __restrict__ out) {
    int idx = blockIdx.x * blockDim.x + threadIdx.x;
    if (idx >= NTOT * HORZ) return;
    int i = idx / HORZ, hor = idx - i * HORZ;
    const float* hr = g_h + (size_t)i * HD;
    float s = bo[hor];
#pragma unroll 8
    for (int k = 0; k < HD; k++) s = fmaf(hr[k], Wo[k * HORZ + hor], s);
    int b = i / NNODE, n = i - b * NNODE;
    out[(size_t)(b * HORZ + hor) * NNODE + n] = s;
}

// ---------------- launch ----------------
extern "C" void kernel_launch(void* const* d_in, const int* in_sizes, int n_in,
                              void* d_out, int out_size) {
    const float* x  = (const float*)d_in[0];
    const void*  ei = d_in[1];
    const float* W1 = (const float*)d_in[2];
    const float* b1 = (const float*)d_in[3];
    const float* W2 = (const float*)d_in[4];
    const float* b2 = (const float*)d_in[5];
    const float* Wz = (const float*)d_in[6];
    const float* bz = (const float*)d_in[7];
    const float* Wr = (const float*)d_in[8];
    const float* br = (const float*)d_in[9];
    const float* Wc = (const float*)d_in[10];
    const float* bc = (const float*)d_in[11];
    const float* Wo = (const float*)d_in[12];
    const float* bo = (const float*)d_in[13];
    float* out = (float*)d_out;
    (void)in_sizes; (void)n_in; (void)out_size;

    const int SMEM = 2 * 128 * EKP * 2;   // 77824
    cudaFuncSetAttribute(cell_kernel, cudaFuncAttributeMaxDynamicSharedMemorySize, SMEM);

    zero_h_kernel<<<(NTOT * HD + 1023) / 1024, 1024>>>();
    zero_counts_kernel<<<(2 * NNODE + 255) / 256, 256>>>();
    detect_dtype_kernel<<<(2 * NEDGE + 255) / 256, 256>>>(ei);
    set_is64_kernel<<<1, 1>>>();
    count_edges_kernel<<<(NEDGE + 255) / 256, 256>>>(ei);
    norm_kernel<<<(NEDGE + 255) / 256, 256>>>(ei);
    scan_kernel<<<1, 1024>>>();
    fill_kernel<<<(NEDGE + 255) / 256, 256>>>(ei);
    build_zr_fold_kernel<<<(7 * 256 + 255) / 256, 256>>>(W1, b1, Wz, bz, Wr, br);
    build_c_fold_kernel<<<(7 * HD + 255) / 256, 256>>>(W1, b1, Wc, bc);
    build_bext_kernel<<<(6 * 128 * 144 + 255) / 256, 256>>>(W2, Wz, Wr, Wc, b2);

    for (int t = 0; t < TSTEPS; t++) {
        const float* xt0 = x + (size_t)t * NNODE * INF;   // batch 0, timestep t
        prop2_kernel<<<(NNODE * INF + 127) / 128, 128>>>(xt0, 0);
        prop2_kernel<<<(NNODE * INF + 127) / 128, 128>>>(xt0, 1);
        prop128_kernel<<<NNODE, HD>>>(0);
        prop128_kernel<<<NNODE, HD>>>(1);
        cell_kernel<<<NTOT / 128, 256, SMEM>>>(x, t);
    }

    out_kernel<<<(NTOT * HORZ + 255) / 256, 256>>>(Wo, bo, out);
}